// round 2
// baseline (speedup 1.0000x reference)
#include <cuda_runtime.h>
#include <math.h>

// ---------------------------------------------------------------------------
// Problem constants (fixed by setup_inputs)
// ---------------------------------------------------------------------------
#define B_   4
#define S_   1536
#define H_   1024
#define NH_  8
#define HD_  128
#define FF_  4096
#define M_   (B_ * S_)          /* 6144 rows total */

#define XSZ  6291456ull         /* M_ * H_ floats */
#define HSZ  25165824ull        /* M_ * FF_ floats */

// Scratch: xn(=ao), qb, kb, vb, rb, xb : 6 * XSZ ; hb : HSZ   => 252 MB
__device__ float g_buf[6 * XSZ + HSZ];

// ---------------------------------------------------------------------------
// Block-wide all-reduce (blockDim.x == 256)
// ---------------------------------------------------------------------------
__device__ __forceinline__ float blockAllReduceSum(float v) {
    __shared__ float sh[9];
    #pragma unroll
    for (int o = 16; o > 0; o >>= 1) v += __shfl_xor_sync(0xffffffffu, v, o);
    if ((threadIdx.x & 31) == 0) sh[threadIdx.x >> 5] = v;
    __syncthreads();
    if (threadIdx.x < 32) {
        float x = (threadIdx.x < 8) ? sh[threadIdx.x] : 0.f;
        #pragma unroll
        for (int o = 4; o > 0; o >>= 1) x += __shfl_xor_sync(0xffffffffu, x, o);
        if (threadIdx.x == 0) sh[8] = x;
    }
    __syncthreads();
    float r = sh[8];
    __syncthreads();
    return r;
}

// ---------------------------------------------------------------------------
// LayerNorm: one block per row of 1024, 256 threads, float4 per thread.
// If g2 != nullptr, rows with (row % S_) >= *nvp use (g2, b2) (text params).
// ---------------------------------------------------------------------------
__global__ void ln_kernel(const float* __restrict__ x,
                          const float* __restrict__ g1, const float* __restrict__ b1,
                          const float* __restrict__ g2, const float* __restrict__ b2,
                          const int* __restrict__ nvp,
                          float* __restrict__ out)
{
    int row = blockIdx.x;
    const float* gg = g1;
    const float* bb = b1;
    if (g2 != nullptr) {
        if ((row % S_) >= __ldg(nvp)) { gg = g2; bb = b2; }
    }
    int t = threadIdx.x;
    const float4* xr = reinterpret_cast<const float4*>(x + (size_t)row * H_);
    float4 v = xr[t];
    float s = v.x + v.y + v.z + v.w;
    s = blockAllReduceSum(s);
    float mu = s * (1.f / H_);
    float dx = v.x - mu, dy = v.y - mu, dz = v.z - mu, dw = v.w - mu;
    float q = dx * dx + dy * dy + dz * dz + dw * dw;
    q = blockAllReduceSum(q);
    float rs = rsqrtf(q * (1.f / H_) + 1e-5f);
    float4 gv = reinterpret_cast<const float4*>(gg)[t];
    float4 bv = reinterpret_cast<const float4*>(bb)[t];
    float4 o;
    o.x = dx * rs * gv.x + bv.x;
    o.y = dy * rs * gv.y + bv.y;
    o.z = dz * rs * gv.z + bv.z;
    o.w = dw * rs * gv.w + bv.w;
    reinterpret_cast<float4*>(out + (size_t)row * H_)[t] = o;
}

// ---------------------------------------------------------------------------
// Templated 128x128x8 fp32 GEMM (NT), 256 threads, 8x8 acc per thread.
// MODE 0: C = A @ W^T + bias, permuted store into [B*NH, S, HD]   (QKV)
// MODE 3: C = res + A @ W^T + bias (opt. per-tile weight select)  (proj/ffn2)
// MODE 4: C = gelu(A @ W^T + bias) (per-tile weight select)       (ffn1)
// All dims are multiples of tile sizes -> no bounds checks.
// ---------------------------------------------------------------------------
template<int MODE>
__global__ void __launch_bounds__(256, 2)
gemm_k(const float* __restrict__ A, const float* __restrict__ W,
       const float* __restrict__ bias, const float* __restrict__ res,
       float* __restrict__ C, int M, int N, int K,
       const float* __restrict__ W2, const float* __restrict__ bias2,
       const int* __restrict__ nvp)
{
    __shared__ float As[8][128];
    __shared__ float Bs[8][128];
    const int t  = threadIdx.x;
    const int tx = t & 15;
    const int ty = t >> 4;
    const int bn0 = blockIdx.x * 128;
    const int bm0 = blockIdx.y * 128;

    const float* Wp = W;
    const float* bp = bias;
    if ((MODE == 3 || MODE == 4) && W2 != nullptr) {
        int nv = __ldg(nvp);
        if ((bm0 % S_) >= nv) { Wp = W2; bp = bias2; }
    }

    const int rA = t >> 1;          // 0..127
    const int cA = (t & 1) * 4;     // 0 or 4

    float acc[8][8];
    #pragma unroll
    for (int i = 0; i < 8; i++)
        #pragma unroll
        for (int j = 0; j < 8; j++) acc[i][j] = 0.f;

    for (int k0 = 0; k0 < K; k0 += 8) {
        float4 av = *reinterpret_cast<const float4*>(A  + (size_t)(bm0 + rA) * K + (k0 + cA));
        As[cA + 0][rA] = av.x; As[cA + 1][rA] = av.y;
        As[cA + 2][rA] = av.z; As[cA + 3][rA] = av.w;
        float4 wv = *reinterpret_cast<const float4*>(Wp + (size_t)(bn0 + rA) * K + (k0 + cA));
        Bs[cA + 0][rA] = wv.x; Bs[cA + 1][rA] = wv.y;
        Bs[cA + 2][rA] = wv.z; Bs[cA + 3][rA] = wv.w;
        __syncthreads();
        #pragma unroll
        for (int kk = 0; kk < 8; kk++) {
            float4 a0 = *reinterpret_cast<const float4*>(&As[kk][ty * 4]);
            float4 a1 = *reinterpret_cast<const float4*>(&As[kk][64 + ty * 4]);
            float4 b0 = *reinterpret_cast<const float4*>(&Bs[kk][tx * 4]);
            float4 b1 = *reinterpret_cast<const float4*>(&Bs[kk][64 + tx * 4]);
            float af[8] = {a0.x, a0.y, a0.z, a0.w, a1.x, a1.y, a1.z, a1.w};
            float bf[8] = {b0.x, b0.y, b0.z, b0.w, b1.x, b1.y, b1.z, b1.w};
            #pragma unroll
            for (int i = 0; i < 8; i++)
                #pragma unroll
                for (int j = 0; j < 8; j++)
                    acc[i][j] = fmaf(af[i], bf[j], acc[i][j]);
        }
        __syncthreads();
    }

    int rows[8], cols[8];
    #pragma unroll
    for (int i = 0; i < 4; i++) {
        rows[i]     = bm0 + ty * 4 + i;
        rows[i + 4] = bm0 + 64 + ty * 4 + i;
        cols[i]     = bn0 + tx * 4 + i;
        cols[i + 4] = bn0 + 64 + tx * 4 + i;
    }

    #pragma unroll
    for (int i = 0; i < 8; i++) {
        #pragma unroll
        for (int j = 0; j < 8; j++) {
            int m = rows[i], n = cols[j];
            float vacc = acc[i][j];
            if (MODE == 0) {
                int b = m / S_, s = m % S_;
                int hh = n >> 7, d = n & 127;
                C[((size_t)(b * NH_ + hh) * S_ + s) * HD_ + d] = vacc + __ldg(&bp[n]);
            } else if (MODE == 3) {
                size_t idx = (size_t)m * N + n;
                C[idx] = res[idx] + vacc + __ldg(&bp[n]);
            } else {
                float x = vacc + __ldg(&bp[n]);
                C[(size_t)m * N + n] = 0.5f * x * (1.f + erff(x * 0.7071067811865475f));
            }
        }
    }
}

// ---------------------------------------------------------------------------
// Fused attention (flash style). Grid: (S_/128, B_*NH_), 256 threads, occ 1.
// Q,K,V in [B*NH, S, HD]; O written to [B, S, H]. Mask applied from int mask.
// Dynamic smem: As(8x128) + Bs(8x128) + Ps(128x132) floats = 75776 bytes.
// ---------------------------------------------------------------------------
#define FLASH_SMEM (2048 + 128 * 132) * 4

__global__ void __launch_bounds__(256, 1)
flash_kernel(const float* __restrict__ Q, const float* __restrict__ K,
             const float* __restrict__ V, const int* __restrict__ mask,
             float* __restrict__ O)
{
    extern __shared__ float sh[];
    float (*As)[128] = reinterpret_cast<float(*)[128]>(sh);
    float (*Bs)[128] = reinterpret_cast<float(*)[128]>(sh + 1024);
    float (*Ps)[132] = reinterpret_cast<float(*)[132]>(sh + 2048);

    const int t  = threadIdx.x;
    const int tx = t & 15;
    const int ty = t >> 4;
    const int qt = blockIdx.x;
    const int z  = blockIdx.y;
    const int b  = z >> 3, h = z & 7;
    const int bm0 = qt * 128;

    const float* Qp = Q + (size_t)z * S_ * HD_;
    const float* Kp = K + (size_t)z * S_ * HD_;
    const float* Vp = V + (size_t)z * S_ * HD_;
    const int*   Mp = mask + (size_t)b * S_ * S_;

    const int rA = t >> 1;
    const int cA = (t & 1) * 4;
    const int rB = t >> 5;
    const int cB = (t & 31) * 4;

    const float SC = 0.08838834764831845f;   /* HD^-0.5 */

    float o[8][8];
    float m_i[8], l_i[8];
    int rowl[8];
    #pragma unroll
    for (int i = 0; i < 8; i++) {
        m_i[i] = -INFINITY; l_i[i] = 0.f;
        rowl[i] = (i < 4) ? (ty * 4 + i) : (64 + ty * 4 + (i - 4));
        #pragma unroll
        for (int j = 0; j < 8; j++) o[i][j] = 0.f;
    }

    for (int kt = 0; kt < S_ / 128; kt++) {
        const int bn0 = kt * 128;

        // ---- S = Q @ K^T over HD=128 ----
        float acc[8][8];
        #pragma unroll
        for (int i = 0; i < 8; i++)
            #pragma unroll
            for (int j = 0; j < 8; j++) acc[i][j] = 0.f;

        for (int k0 = 0; k0 < HD_; k0 += 8) {
            float4 av = *reinterpret_cast<const float4*>(Qp + (size_t)(bm0 + rA) * HD_ + (k0 + cA));
            As[cA + 0][rA] = av.x; As[cA + 1][rA] = av.y;
            As[cA + 2][rA] = av.z; As[cA + 3][rA] = av.w;
            float4 kv = *reinterpret_cast<const float4*>(Kp + (size_t)(bn0 + rA) * HD_ + (k0 + cA));
            Bs[cA + 0][rA] = kv.x; Bs[cA + 1][rA] = kv.y;
            Bs[cA + 2][rA] = kv.z; Bs[cA + 3][rA] = kv.w;
            __syncthreads();
            #pragma unroll
            for (int kk = 0; kk < 8; kk++) {
                float4 a0 = *reinterpret_cast<const float4*>(&As[kk][ty * 4]);
                float4 a1 = *reinterpret_cast<const float4*>(&As[kk][64 + ty * 4]);
                float4 b0 = *reinterpret_cast<const float4*>(&Bs[kk][tx * 4]);
                float4 b1 = *reinterpret_cast<const float4*>(&Bs[kk][64 + tx * 4]);
                float af[8] = {a0.x, a0.y, a0.z, a0.w, a1.x, a1.y, a1.z, a1.w};
                float bf[8] = {b0.x, b0.y, b0.z, b0.w, b1.x, b1.y, b1.z, b1.w};
                #pragma unroll
                for (int i = 0; i < 8; i++)
                    #pragma unroll
                    for (int j = 0; j < 8; j++)
                        acc[i][j] = fmaf(af[i], bf[j], acc[i][j]);
            }
            __syncthreads();
        }

        // ---- scale + mask + online softmax ----
        #pragma unroll
        for (int i = 0; i < 8; i++) {
            const int* mrow = Mp + (size_t)(bm0 + rowl[i]) * S_ + bn0;
            int4 m0 = *reinterpret_cast<const int4*>(mrow + tx * 4);
            int4 m1 = *reinterpret_cast<const int4*>(mrow + 64 + tx * 4);
            acc[i][0] = (m0.x > 0) ? acc[i][0] * SC : -INFINITY;
            acc[i][1] = (m0.y > 0) ? acc[i][1] * SC : -INFINITY;
            acc[i][2] = (m0.z > 0) ? acc[i][2] * SC : -INFINITY;
            acc[i][3] = (m0.w > 0) ? acc[i][3] * SC : -INFINITY;
            acc[i][4] = (m1.x > 0) ? acc[i][4] * SC : -INFINITY;
            acc[i][5] = (m1.y > 0) ? acc[i][5] * SC : -INFINITY;
            acc[i][6] = (m1.z > 0) ? acc[i][6] * SC : -INFINITY;
            acc[i][7] = (m1.w > 0) ? acc[i][7] * SC : -INFINITY;

            float mx = acc[i][0];
            #pragma unroll
            for (int j = 1; j < 8; j++) mx = fmaxf(mx, acc[i][j]);
            #pragma unroll
            for (int off = 8; off > 0; off >>= 1)
                mx = fmaxf(mx, __shfl_xor_sync(0xffffffffu, mx, off));
            float mnew = fmaxf(m_i[i], mx);
            float corr = (m_i[i] == -INFINITY) ? 0.f : __expf(m_i[i] - mnew);

            float s = 0.f;
            #pragma unroll
            for (int j = 0; j < 8; j++) {
                float p = __expf(acc[i][j] - mnew);
                acc[i][j] = p;
                s += p;
            }
            #pragma unroll
            for (int off = 8; off > 0; off >>= 1)
                s += __shfl_xor_sync(0xffffffffu, s, off);

            l_i[i] = l_i[i] * corr + s;
            m_i[i] = mnew;
            #pragma unroll
            for (int j = 0; j < 8; j++) o[i][j] *= corr;
        }

        // ---- stage P into smem (Ps[q_local][k_local]) ----
        #pragma unroll
        for (int i = 0; i < 8; i++) {
            *reinterpret_cast<float4*>(&Ps[rowl[i]][tx * 4]) =
                make_float4(acc[i][0], acc[i][1], acc[i][2], acc[i][3]);
            *reinterpret_cast<float4*>(&Ps[rowl[i]][64 + tx * 4]) =
                make_float4(acc[i][4], acc[i][5], acc[i][6], acc[i][7]);
        }
        __syncthreads();

        // ---- O += P @ V (V staged 8 rows at a time into Bs) ----
        for (int kv0 = 0; kv0 < 128; kv0 += 8) {
            float4 vv = *reinterpret_cast<const float4*>(Vp + (size_t)(bn0 + kv0 + rB) * HD_ + cB);
            *reinterpret_cast<float4*>(&Bs[rB][cB]) = vv;
            __syncthreads();
            #pragma unroll
            for (int kk = 0; kk < 8; kk++) {
                float4 b0 = *reinterpret_cast<const float4*>(&Bs[kk][tx * 4]);
                float4 b1 = *reinterpret_cast<const float4*>(&Bs[kk][64 + tx * 4]);
                float bf[8] = {b0.x, b0.y, b0.z, b0.w, b1.x, b1.y, b1.z, b1.w};
                #pragma unroll
                for (int i = 0; i < 8; i++) {
                    float a = Ps[rowl[i]][kv0 + kk];
                    #pragma unroll
                    for (int j = 0; j < 8; j++)
                        o[i][j] = fmaf(a, bf[j], o[i][j]);
                }
            }
            __syncthreads();
        }
    }

    // ---- epilogue: normalize and store to [B, S, H] ----
    #pragma unroll
    for (int i = 0; i < 8; i++) {
        float inv = 1.f / l_i[i];
        float* orow = O + ((size_t)b * S_ + (bm0 + rowl[i])) * H_ + h * HD_;
        *reinterpret_cast<float4*>(orow + tx * 4) =
            make_float4(o[i][0] * inv, o[i][1] * inv, o[i][2] * inv, o[i][3] * inv);
        *reinterpret_cast<float4*>(orow + 64 + tx * 4) =
            make_float4(o[i][4] * inv, o[i][5] * inv, o[i][6] * inv, o[i][7] * inv);
    }
}

// ---------------------------------------------------------------------------
// Host driver: 6 layers. Graph-capturable: kernel launches only.
// ---------------------------------------------------------------------------
extern "C" void kernel_launch(void* const* d_in, const int* in_sizes, int n_in,
                              void* d_out, int out_size)
{
    const float* fused  = (const float*)d_in[0];
    const int*   mask   = (const int*)  d_in[1];
    const int*   nvp    = (const int*)  d_in[2];
    /* d_in[3] = n_text (unused) */
    const float* ln1_g  = (const float*)d_in[4];
    const float* ln1_b  = (const float*)d_in[5];
    const float* wq     = (const float*)d_in[6];
    const float* bq     = (const float*)d_in[7];
    const float* wk     = (const float*)d_in[8];
    const float* bk     = (const float*)d_in[9];
    const float* wv     = (const float*)d_in[10];
    const float* bv     = (const float*)d_in[11];
    const float* wm     = (const float*)d_in[12];
    const float* bmp    = (const float*)d_in[13];
    const float* ln2v_g = (const float*)d_in[14];
    const float* ln2v_b = (const float*)d_in[15];
    const float* fv1_w  = (const float*)d_in[16];
    const float* fv1_b  = (const float*)d_in[17];
    const float* fv2_w  = (const float*)d_in[18];
    const float* fv2_b  = (const float*)d_in[19];
    const float* ln2t_g = (const float*)d_in[20];
    const float* ln2t_b = (const float*)d_in[21];
    const float* ft1_w  = (const float*)d_in[22];
    const float* ft1_b  = (const float*)d_in[23];
    const float* ft2_w  = (const float*)d_in[24];
    const float* ft2_b  = (const float*)d_in[25];

    float* base = nullptr;
    cudaGetSymbolAddress((void**)&base, g_buf);
    float* xn  = base;            // LN output; reused as attention output
    float* qb  = base + 1 * XSZ;
    float* kb  = base + 2 * XSZ;
    float* vb  = base + 3 * XSZ;
    float* rb  = base + 4 * XSZ;
    float* xb  = base + 5 * XSZ;
    float* hb  = base + 6 * XSZ;

    cudaFuncSetAttribute(flash_kernel,
                         cudaFuncAttributeMaxDynamicSharedMemorySize, FLASH_SMEM);

    dim3 thr(256);
    dim3 gProj(H_ / 128, M_ / 128);            // (8, 48)
    dim3 gF1(FF_ / 128, M_ / 128);             // (32, 48)
    dim3 gFl(S_ / 128, B_ * NH_);              // (12, 32)

    const float* xc = fused;
    for (int layer = 0; layer < 6; layer++) {
        float* xnext = (layer == 5) ? (float*)d_out : xb;

        // ---- attention block ----
        ln_kernel<<<M_, thr>>>(xc, ln1_g, ln1_b, nullptr, nullptr, nullptr, xn);
        gemm_k<0><<<gProj, thr>>>(xn, wq, bq, nullptr, qb, M_, H_, H_, nullptr, nullptr, nullptr);
        gemm_k<0><<<gProj, thr>>>(xn, wk, bk, nullptr, kb, M_, H_, H_, nullptr, nullptr, nullptr);
        gemm_k<0><<<gProj, thr>>>(xn, wv, bv, nullptr, vb, M_, H_, H_, nullptr, nullptr, nullptr);
        flash_kernel<<<gFl, thr, FLASH_SMEM>>>(qb, kb, vb, mask, xn);
        gemm_k<3><<<gProj, thr>>>(xn, wm, bmp, xc, rb, M_, H_, H_, nullptr, nullptr, nullptr);

        // ---- split FFN block (video/text weights selected per M-tile) ----
        ln_kernel<<<M_, thr>>>(rb, ln2v_g, ln2v_b, ln2t_g, ln2t_b, nvp, xn);
        gemm_k<4><<<gF1, thr>>>(xn, fv1_w, fv1_b, nullptr, hb, M_, FF_, H_, ft1_w, ft1_b, nvp);
        gemm_k<3><<<gProj, thr>>>(hb, fv2_w, fv2_b, rb, xnext, M_, H_, FF_, ft2_w, ft2_b, nvp);

        xc = xnext;
    }
}

// round 5
// speedup vs baseline: 1.9982x; 1.9982x over previous
#include <cuda_runtime.h>
#include <math.h>
#include <stdint.h>

// ---------------------------------------------------------------------------
// Problem constants (fixed by setup_inputs)
// ---------------------------------------------------------------------------
#define B_   4
#define S_   1536
#define H_   1024
#define NH_  8
#define HD_  128
#define FF_  4096
#define M_   (B_ * S_)          /* 6144 rows total */

#define XSZ  6291456ull         /* M_ * H_ floats */
#define HSZ  25165824ull        /* M_ * FF_ floats */
#define WSQ  ((size_t)H_ * H_)        /* 1M  */
#define WSF  ((size_t)FF_ * H_)       /* 4M  */

// Scratch: xn, qb, kb, vb, rb, xb : 6*XSZ ; hb : HSZ ; tf32 weights : 4*WSQ+4*WSF
__device__ float g_buf[6 * XSZ + HSZ + 4 * WSQ + 4 * WSF];

// ---------------------------------------------------------------------------
// tf32 helpers
// ---------------------------------------------------------------------------
__device__ __forceinline__ float tf32r(float x) {
    uint32_t u;
    asm("cvt.rna.tf32.f32 %0, %1;" : "=r"(u) : "f"(x));
    return __uint_as_float(u);
}

__global__ void round_tf32_k(const float* __restrict__ in, float* __restrict__ out, int n4)
{
    int i = blockIdx.x * blockDim.x + threadIdx.x;
    if (i < n4) {
        float4 v = reinterpret_cast<const float4*>(in)[i];
        v.x = tf32r(v.x); v.y = tf32r(v.y); v.z = tf32r(v.z); v.w = tf32r(v.w);
        reinterpret_cast<float4*>(out)[i] = v;
    }
}

// ---------------------------------------------------------------------------
// cp.async helpers
// ---------------------------------------------------------------------------
__device__ __forceinline__ void cp16(void* dst, const void* src) {
    uint32_t d = (uint32_t)__cvta_generic_to_shared(dst);
    asm volatile("cp.async.cg.shared.global [%0], [%1], 16;\n" :: "r"(d), "l"(src));
}
#define CP_COMMIT() asm volatile("cp.async.commit_group;\n")
#define CP_WAIT0()  asm volatile("cp.async.wait_group 0;\n")

// ---------------------------------------------------------------------------
// Block-wide all-reduce (blockDim.x == 256)
// ---------------------------------------------------------------------------
__device__ __forceinline__ float blockAllReduceSum(float v) {
    __shared__ float sh[9];
    #pragma unroll
    for (int o = 16; o > 0; o >>= 1) v += __shfl_xor_sync(0xffffffffu, v, o);
    if ((threadIdx.x & 31) == 0) sh[threadIdx.x >> 5] = v;
    __syncthreads();
    if (threadIdx.x < 32) {
        float x = (threadIdx.x < 8) ? sh[threadIdx.x] : 0.f;
        #pragma unroll
        for (int o = 4; o > 0; o >>= 1) x += __shfl_xor_sync(0xffffffffu, x, o);
        if (threadIdx.x == 0) sh[8] = x;
    }
    __syncthreads();
    float r = sh[8];
    __syncthreads();
    return r;
}

// ---------------------------------------------------------------------------
// LayerNorm: one block per row of 1024, 256 threads, float4 per thread.
// Output rounded to tf32 (it is only ever consumed as a GEMM A operand).
// ---------------------------------------------------------------------------
__global__ void ln_kernel(const float* __restrict__ x,
                          const float* __restrict__ g1, const float* __restrict__ b1,
                          const float* __restrict__ g2, const float* __restrict__ b2,
                          const int* __restrict__ nvp,
                          float* __restrict__ out)
{
    int row = blockIdx.x;
    const float* gg = g1;
    const float* bb = b1;
    if (g2 != nullptr) {
        if ((row % S_) >= __ldg(nvp)) { gg = g2; bb = b2; }
    }
    int t = threadIdx.x;
    const float4* xr = reinterpret_cast<const float4*>(x + (size_t)row * H_);
    float4 v = xr[t];
    float s = v.x + v.y + v.z + v.w;
    s = blockAllReduceSum(s);
    float mu = s * (1.f / H_);
    float dx = v.x - mu, dy = v.y - mu, dz = v.z - mu, dw = v.w - mu;
    float q = dx * dx + dy * dy + dz * dz + dw * dw;
    q = blockAllReduceSum(q);
    float rs = rsqrtf(q * (1.f / H_) + 1e-5f);
    float4 gv = reinterpret_cast<const float4*>(gg)[t];
    float4 bv = reinterpret_cast<const float4*>(bb)[t];
    float4 o;
    o.x = tf32r(dx * rs * gv.x + bv.x);
    o.y = tf32r(dy * rs * gv.y + bv.y);
    o.z = tf32r(dz * rs * gv.z + bv.z);
    o.w = tf32r(dw * rs * gv.w + bv.w);
    reinterpret_cast<float4*>(out + (size_t)row * H_)[t] = o;
}

// ---------------------------------------------------------------------------
// Tensor-core tf32 GEMM: C = A @ W^T (+epilogue).  128x128x32 tile,
// 256 threads = 8 warps (2 M x 4 N), warp tile 64x32, mma.m16n8k8.tf32.
// MODE 0: +bias, permuted store into [B*NH, S, HD]       (QKV)
// MODE 3: res + acc + bias (opt. per-tile weight select)  (proj/ffn2)
// MODE 4: gelu(acc + bias), tf32-rounded output           (ffn1)
// Inputs A and W must already be tf32-rounded.
// All dims are multiples of tile sizes -> no bounds checks.
// ---------------------------------------------------------------------------
#define ASTR 36
#define GEMM_SMEM (2 * 2 * 128 * ASTR * 4)   /* 73728 bytes */

template<int MODE>
__global__ void __launch_bounds__(256)
gemm_tc(const float* __restrict__ A, const float* __restrict__ W,
        const float* __restrict__ bias, const float* __restrict__ res,
        float* __restrict__ C, int M, int N, int K,
        const float* __restrict__ W2, const float* __restrict__ bias2,
        const int* __restrict__ nvp)
{
    extern __shared__ float sm[];
    float* As = sm;                       // [2][128][ASTR]
    float* Bs = sm + 2 * 128 * ASTR;      // [2][128][ASTR]

    const int t    = threadIdx.x;
    const int lane = t & 31;
    const int warp = t >> 5;
    const int wm   = warp & 1;            // 0..1
    const int wn   = warp >> 1;           // 0..3
    const int g    = lane >> 2;           // groupID 0..7
    const int tg   = lane & 3;            // threadID_in_group 0..3
    const int bn0  = blockIdx.x * 128;
    const int bm0  = blockIdx.y * 128;

    const float* Wp = W;
    const float* bp = bias;
    if ((MODE == 3 || MODE == 4) && W2 != nullptr) {
        if ((bm0 % S_) >= __ldg(nvp)) { Wp = W2; bp = bias2; }
    }

    float acc[4][4][4];
    #pragma unroll
    for (int i = 0; i < 4; i++)
        #pragma unroll
        for (int j = 0; j < 4; j++)
            #pragma unroll
            for (int c = 0; c < 4; c++) acc[i][j][c] = 0.f;

    const int nk = K >> 5;

    // global->smem loader: 128 rows x 8 float4 per operand, 4 f4 per thread
    auto load_tile = [&](int buf, int k0) {
        #pragma unroll
        for (int j = 0; j < 4; j++) {
            int i  = t + 256 * j;
            int r  = i >> 3;
            int c4 = (i & 7) * 4;
            cp16(&As[buf * 128 * ASTR + r * ASTR + c4],
                 A  + (size_t)(bm0 + r) * K + k0 + c4);
            cp16(&Bs[buf * 128 * ASTR + r * ASTR + c4],
                 Wp + (size_t)(bn0 + r) * K + k0 + c4);
        }
    };

    load_tile(0, 0);
    CP_COMMIT();

    for (int kt = 0; kt < nk; kt++) {
        CP_WAIT0();
        __syncthreads();
        if (kt + 1 < nk) { load_tile((kt + 1) & 1, (kt + 1) << 5); CP_COMMIT(); }

        const float* Ab = As + (kt & 1) * 128 * ASTR;
        const float* Bb = Bs + (kt & 1) * 128 * ASTR;

        #pragma unroll
        for (int ks = 0; ks < 4; ks++) {
            uint32_t af[4][4];
            #pragma unroll
            for (int mt = 0; mt < 4; mt++) {
                int r = wm * 64 + mt * 16 + g;
                int c = ks * 8 + tg;
                af[mt][0] = __float_as_uint(Ab[r * ASTR + c]);
                af[mt][1] = __float_as_uint(Ab[(r + 8) * ASTR + c]);
                af[mt][2] = __float_as_uint(Ab[r * ASTR + c + 4]);
                af[mt][3] = __float_as_uint(Ab[(r + 8) * ASTR + c + 4]);
            }
            uint32_t bf[4][2];
            #pragma unroll
            for (int nt = 0; nt < 4; nt++) {
                int n = wn * 32 + nt * 8 + g;
                int c = ks * 8 + tg;
                bf[nt][0] = __float_as_uint(Bb[n * ASTR + c]);
                bf[nt][1] = __float_as_uint(Bb[n * ASTR + c + 4]);
            }
            #pragma unroll
            for (int mt = 0; mt < 4; mt++)
                #pragma unroll
                for (int nt = 0; nt < 4; nt++) {
                    asm volatile(
                        "mma.sync.aligned.m16n8k8.row.col.f32.tf32.tf32.f32 "
                        "{%0,%1,%2,%3}, {%4,%5,%6,%7}, {%8,%9}, {%0,%1,%2,%3};\n"
                        : "+f"(acc[mt][nt][0]), "+f"(acc[mt][nt][1]),
                          "+f"(acc[mt][nt][2]), "+f"(acc[mt][nt][3])
                        : "r"(af[mt][0]), "r"(af[mt][1]), "r"(af[mt][2]), "r"(af[mt][3]),
                          "r"(bf[nt][0]), "r"(bf[nt][1]));
                }
        }
        __syncthreads();
    }

    // ---- epilogue ----
    #pragma unroll
    for (int mt = 0; mt < 4; mt++) {
        #pragma unroll
        for (int nt = 0; nt < 4; nt++) {
            int m = bm0 + wm * 64 + mt * 16 + g;
            int n = bn0 + wn * 32 + nt * 8 + tg * 2;
            float2 bb2 = *reinterpret_cast<const float2*>(bp + n);
            #pragma unroll
            for (int h = 0; h < 2; h++) {
                int mr = m + h * 8;
                float vx = acc[mt][nt][h * 2 + 0] + bb2.x;
                float vy = acc[mt][nt][h * 2 + 1] + bb2.y;
                if (MODE == 0) {
                    int b = mr / S_, s = mr % S_;
                    int hh = n >> 7, d = n & 127;
                    *reinterpret_cast<float2*>(
                        C + ((size_t)(b * NH_ + hh) * S_ + s) * HD_ + d) =
                        make_float2(vx, vy);
                } else if (MODE == 3) {
                    size_t idx = (size_t)mr * N + n;
                    float2 r2 = *reinterpret_cast<const float2*>(res + idx);
                    *reinterpret_cast<float2*>(C + idx) =
                        make_float2(r2.x + vx, r2.y + vy);
                } else {
                    float gx = 0.5f * vx * (1.f + erff(vx * 0.7071067811865475f));
                    float gy = 0.5f * vy * (1.f + erff(vy * 0.7071067811865475f));
                    *reinterpret_cast<float2*>(C + (size_t)mr * N + n) =
                        make_float2(tf32r(gx), tf32r(gy));
                }
            }
        }
    }
}

// ---------------------------------------------------------------------------
// Fused attention (flash style, fp32 SIMT). Grid: (S_/128, B_*NH_), 256 thr.
// Q,K,V in [B*NH, S, HD]; O written to [B, S, H] (tf32-rounded: feeds proj).
// ---------------------------------------------------------------------------
#define FLASH_SMEM ((2048 + 128 * 132) * 4)

__global__ void __launch_bounds__(256, 1)
flash_kernel(const float* __restrict__ Q, const float* __restrict__ K,
             const float* __restrict__ V, const int* __restrict__ mask,
             float* __restrict__ O)
{
    extern __shared__ float sh[];
    float (*As)[128] = reinterpret_cast<float(*)[128]>(sh);
    float (*Bs)[128] = reinterpret_cast<float(*)[128]>(sh + 1024);
    float (*Ps)[132] = reinterpret_cast<float(*)[132]>(sh + 2048);

    const int t  = threadIdx.x;
    const int tx = t & 15;
    const int ty = t >> 4;
    const int qt = blockIdx.x;
    const int z  = blockIdx.y;
    const int b  = z >> 3, h = z & 7;
    const int bm0 = qt * 128;

    const float* Qp = Q + (size_t)z * S_ * HD_;
    const float* Kp = K + (size_t)z * S_ * HD_;
    const float* Vp = V + (size_t)z * S_ * HD_;
    const int*   Mp = mask + (size_t)b * S_ * S_;

    const int rA = t >> 1;
    const int cA = (t & 1) * 4;
    const int rB = t >> 5;
    const int cB = (t & 31) * 4;

    const float SC = 0.08838834764831845f;

    float o[8][8];
    float m_i[8], l_i[8];
    int rowl[8];
    #pragma unroll
    for (int i = 0; i < 8; i++) {
        m_i[i] = -INFINITY; l_i[i] = 0.f;
        rowl[i] = (i < 4) ? (ty * 4 + i) : (64 + ty * 4 + (i - 4));
        #pragma unroll
        for (int j = 0; j < 8; j++) o[i][j] = 0.f;
    }

    for (int kt = 0; kt < S_ / 128; kt++) {
        const int bn0 = kt * 128;

        float acc[8][8];
        #pragma unroll
        for (int i = 0; i < 8; i++)
            #pragma unroll
            for (int j = 0; j < 8; j++) acc[i][j] = 0.f;

        for (int k0 = 0; k0 < HD_; k0 += 8) {
            float4 av = *reinterpret_cast<const float4*>(Qp + (size_t)(bm0 + rA) * HD_ + (k0 + cA));
            As[cA + 0][rA] = av.x; As[cA + 1][rA] = av.y;
            As[cA + 2][rA] = av.z; As[cA + 3][rA] = av.w;
            float4 kv = *reinterpret_cast<const float4*>(Kp + (size_t)(bn0 + rA) * HD_ + (k0 + cA));
            Bs[cA + 0][rA] = kv.x; Bs[cA + 1][rA] = kv.y;
            Bs[cA + 2][rA] = kv.z; Bs[cA + 3][rA] = kv.w;
            __syncthreads();
            #pragma unroll
            for (int kk = 0; kk < 8; kk++) {
                float4 a0 = *reinterpret_cast<const float4*>(&As[kk][ty * 4]);
                float4 a1 = *reinterpret_cast<const float4*>(&As[kk][64 + ty * 4]);
                float4 b0 = *reinterpret_cast<const float4*>(&Bs[kk][tx * 4]);
                float4 b1 = *reinterpret_cast<const float4*>(&Bs[kk][64 + tx * 4]);
                float af[8] = {a0.x, a0.y, a0.z, a0.w, a1.x, a1.y, a1.z, a1.w};
                float bf[8] = {b0.x, b0.y, b0.z, b0.w, b1.x, b1.y, b1.z, b1.w};
                #pragma unroll
                for (int i = 0; i < 8; i++)
                    #pragma unroll
                    for (int j = 0; j < 8; j++)
                        acc[i][j] = fmaf(af[i], bf[j], acc[i][j]);
            }
            __syncthreads();
        }

        #pragma unroll
        for (int i = 0; i < 8; i++) {
            const int* mrow = Mp + (size_t)(bm0 + rowl[i]) * S_ + bn0;
            int4 m0 = *reinterpret_cast<const int4*>(mrow + tx * 4);
            int4 m1 = *reinterpret_cast<const int4*>(mrow + 64 + tx * 4);
            acc[i][0] = (m0.x > 0) ? acc[i][0] * SC : -INFINITY;
            acc[i][1] = (m0.y > 0) ? acc[i][1] * SC : -INFINITY;
            acc[i][2] = (m0.z > 0) ? acc[i][2] * SC : -INFINITY;
            acc[i][3] = (m0.w > 0) ? acc[i][3] * SC : -INFINITY;
            acc[i][4] = (m1.x > 0) ? acc[i][4] * SC : -INFINITY;
            acc[i][5] = (m1.y > 0) ? acc[i][5] * SC : -INFINITY;
            acc[i][6] = (m1.z > 0) ? acc[i][6] * SC : -INFINITY;
            acc[i][7] = (m1.w > 0) ? acc[i][7] * SC : -INFINITY;

            float mx = acc[i][0];
            #pragma unroll
            for (int j = 1; j < 8; j++) mx = fmaxf(mx, acc[i][j]);
            #pragma unroll
            for (int off = 8; off > 0; off >>= 1)
                mx = fmaxf(mx, __shfl_xor_sync(0xffffffffu, mx, off));
            float mnew = fmaxf(m_i[i], mx);
            float corr = (m_i[i] == -INFINITY) ? 0.f : __expf(m_i[i] - mnew);

            float s = 0.f;
            #pragma unroll
            for (int j = 0; j < 8; j++) {
                float p = __expf(acc[i][j] - mnew);
                acc[i][j] = p;
                s += p;
            }
            #pragma unroll
            for (int off = 8; off > 0; off >>= 1)
                s += __shfl_xor_sync(0xffffffffu, s, off);

            l_i[i] = l_i[i] * corr + s;
            m_i[i] = mnew;
            #pragma unroll
            for (int j = 0; j < 8; j++) o[i][j] *= corr;
        }

        #pragma unroll
        for (int i = 0; i < 8; i++) {
            *reinterpret_cast<float4*>(&Ps[rowl[i]][tx * 4]) =
                make_float4(acc[i][0], acc[i][1], acc[i][2], acc[i][3]);
            *reinterpret_cast<float4*>(&Ps[rowl[i]][64 + tx * 4]) =
                make_float4(acc[i][4], acc[i][5], acc[i][6], acc[i][7]);
        }
        __syncthreads();

        for (int kv0 = 0; kv0 < 128; kv0 += 8) {
            float4 vv = *reinterpret_cast<const float4*>(Vp + (size_t)(bn0 + kv0 + rB) * HD_ + cB);
            *reinterpret_cast<float4*>(&Bs[rB][cB]) = vv;
            __syncthreads();
            #pragma unroll
            for (int kk = 0; kk < 8; kk++) {
                float4 b0 = *reinterpret_cast<const float4*>(&Bs[kk][tx * 4]);
                float4 b1 = *reinterpret_cast<const float4*>(&Bs[kk][64 + tx * 4]);
                float bf[8] = {b0.x, b0.y, b0.z, b0.w, b1.x, b1.y, b1.z, b1.w};
                #pragma unroll
                for (int i = 0; i < 8; i++) {
                    float a = Ps[rowl[i]][kv0 + kk];
                    #pragma unroll
                    for (int j = 0; j < 8; j++)
                        o[i][j] = fmaf(a, bf[j], o[i][j]);
                }
            }
            __syncthreads();
        }
    }

    #pragma unroll
    for (int i = 0; i < 8; i++) {
        float inv = 1.f / l_i[i];
        float* orow = O + ((size_t)b * S_ + (bm0 + rowl[i])) * H_ + h * HD_;
        *reinterpret_cast<float4*>(orow + tx * 4) =
            make_float4(tf32r(o[i][0] * inv), tf32r(o[i][1] * inv),
                        tf32r(o[i][2] * inv), tf32r(o[i][3] * inv));
        *reinterpret_cast<float4*>(orow + 64 + tx * 4) =
            make_float4(tf32r(o[i][4] * inv), tf32r(o[i][5] * inv),
                        tf32r(o[i][6] * inv), tf32r(o[i][7] * inv));
    }
}

// ---------------------------------------------------------------------------
// Host driver: weight prep + 6 layers. Graph-capturable.
// ---------------------------------------------------------------------------
extern "C" void kernel_launch(void* const* d_in, const int* in_sizes, int n_in,
                              void* d_out, int out_size)
{
    const float* fused  = (const float*)d_in[0];
    const int*   mask   = (const int*)  d_in[1];
    const int*   nvp    = (const int*)  d_in[2];
    const float* ln1_g  = (const float*)d_in[4];
    const float* ln1_b  = (const float*)d_in[5];
    const float* wq     = (const float*)d_in[6];
    const float* bq     = (const float*)d_in[7];
    const float* wk     = (const float*)d_in[8];
    const float* bk     = (const float*)d_in[9];
    const float* wv     = (const float*)d_in[10];
    const float* bv     = (const float*)d_in[11];
    const float* wm     = (const float*)d_in[12];
    const float* bmp    = (const float*)d_in[13];
    const float* ln2v_g = (const float*)d_in[14];
    const float* ln2v_b = (const float*)d_in[15];
    const float* fv1_w  = (const float*)d_in[16];
    const float* fv1_b  = (const float*)d_in[17];
    const float* fv2_w  = (const float*)d_in[18];
    const float* fv2_b  = (const float*)d_in[19];
    const float* ln2t_g = (const float*)d_in[20];
    const float* ln2t_b = (const float*)d_in[21];
    const float* ft1_w  = (const float*)d_in[22];
    const float* ft1_b  = (const float*)d_in[23];
    const float* ft2_w  = (const float*)d_in[24];
    const float* ft2_b  = (const float*)d_in[25];

    float* base = nullptr;
    cudaGetSymbolAddress((void**)&base, g_buf);
    float* xn  = base;            // LN output; reused as attention output
    float* qb  = base + 1 * XSZ;
    float* kb  = base + 2 * XSZ;
    float* vb  = base + 3 * XSZ;
    float* rb  = base + 4 * XSZ;
    float* xb  = base + 5 * XSZ;
    float* hb  = base + 6 * XSZ;
    float* wt  = base + 6 * XSZ + HSZ;
    float* wq_t  = wt;
    float* wk_t  = wt + 1 * WSQ;
    float* wv_t  = wt + 2 * WSQ;
    float* wm_t  = wt + 3 * WSQ;
    float* fv1_t = wt + 4 * WSQ;
    float* ft1_t = fv1_t + WSF;
    float* fv2_t = ft1_t + WSF;
    float* ft2_t = fv2_t + WSF;

    cudaFuncSetAttribute(flash_kernel,
                         cudaFuncAttributeMaxDynamicSharedMemorySize, FLASH_SMEM);
    cudaFuncSetAttribute(gemm_tc<0>,
                         cudaFuncAttributeMaxDynamicSharedMemorySize, GEMM_SMEM);
    cudaFuncSetAttribute(gemm_tc<3>,
                         cudaFuncAttributeMaxDynamicSharedMemorySize, GEMM_SMEM);
    cudaFuncSetAttribute(gemm_tc<4>,
                         cudaFuncAttributeMaxDynamicSharedMemorySize, GEMM_SMEM);

    // ---- one-time tf32 weight prep (captured; deterministic) ----
    {
        int nq4 = (int)(WSQ / 4), nf4 = (int)(WSF / 4);
        int tq = 256, gq = (nq4 + tq - 1) / tq, gf = (nf4 + tq - 1) / tq;
        round_tf32_k<<<gq, tq>>>(wq, wq_t, nq4);
        round_tf32_k<<<gq, tq>>>(wk, wk_t, nq4);
        round_tf32_k<<<gq, tq>>>(wv, wv_t, nq4);
        round_tf32_k<<<gq, tq>>>(wm, wm_t, nq4);
        round_tf32_k<<<gf, tq>>>(fv1_w, fv1_t, nf4);
        round_tf32_k<<<gf, tq>>>(ft1_w, ft1_t, nf4);
        round_tf32_k<<<gf, tq>>>(fv2_w, fv2_t, nf4);
        round_tf32_k<<<gf, tq>>>(ft2_w, ft2_t, nf4);
    }

    dim3 thr(256);
    dim3 gProj(H_ / 128, M_ / 128);            // (8, 48)
    dim3 gF1(FF_ / 128, M_ / 128);             // (32, 48)
    dim3 gFl(S_ / 128, B_ * NH_);              // (12, 32)

    const float* xc = fused;
    for (int layer = 0; layer < 6; layer++) {
        float* xnext = (layer == 5) ? (float*)d_out : xb;

        // ---- attention block ----
        ln_kernel<<<M_, thr>>>(xc, ln1_g, ln1_b, nullptr, nullptr, nullptr, xn);
        gemm_tc<0><<<gProj, thr, GEMM_SMEM>>>(xn, wq_t, bq, nullptr, qb, M_, H_, H_, nullptr, nullptr, nullptr);
        gemm_tc<0><<<gProj, thr, GEMM_SMEM>>>(xn, wk_t, bk, nullptr, kb, M_, H_, H_, nullptr, nullptr, nullptr);
        gemm_tc<0><<<gProj, thr, GEMM_SMEM>>>(xn, wv_t, bv, nullptr, vb, M_, H_, H_, nullptr, nullptr, nullptr);
        flash_kernel<<<gFl, thr, FLASH_SMEM>>>(qb, kb, vb, mask, xn);
        gemm_tc<3><<<gProj, thr, GEMM_SMEM>>>(xn, wm_t, bmp, xc, rb, M_, H_, H_, nullptr, nullptr, nullptr);

        // ---- split FFN block (video/text weights selected per M-tile) ----
        ln_kernel<<<M_, thr>>>(rb, ln2v_g, ln2v_b, ln2t_g, ln2t_b, nvp, xn);
        gemm_tc<4><<<gF1, thr, GEMM_SMEM>>>(xn, fv1_t, fv1_b, nullptr, hb, M_, FF_, H_, ft1_t, ft1_b, nvp);
        gemm_tc<3><<<gProj, thr, GEMM_SMEM>>>(hb, fv2_t, fv2_b, rb, xnext, M_, H_, FF_, ft2_t, ft2_b, nvp);

        xc = xnext;
    }
}

// round 6
// speedup vs baseline: 3.1041x; 1.5535x over previous
#include <cuda_runtime.h>
#include <math.h>
#include <stdint.h>

// ---------------------------------------------------------------------------
// Problem constants (fixed by setup_inputs)
// ---------------------------------------------------------------------------
#define B_   4
#define S_   1536
#define H_   1024
#define NH_  8
#define HD_  128
#define FF_  4096
#define M_   (B_ * S_)          /* 6144 rows total */

#define XSZ  6291456ull         /* M_ * H_ floats */
#define HSZ  25165824ull        /* M_ * FF_ floats */
#define WSQ  ((size_t)H_ * H_)
#define WSF  ((size_t)FF_ * H_)

__device__ float g_buf[6 * XSZ + HSZ + 4 * WSQ + 4 * WSF];

// ---------------------------------------------------------------------------
// tf32 helpers
// ---------------------------------------------------------------------------
__device__ __forceinline__ float tf32r(float x) {
    uint32_t u;
    asm("cvt.rna.tf32.f32 %0, %1;" : "=r"(u) : "f"(x));
    return __uint_as_float(u);
}

__global__ void round_tf32_k(const float* __restrict__ in, float* __restrict__ out, int n4)
{
    int i = blockIdx.x * blockDim.x + threadIdx.x;
    if (i < n4) {
        float4 v = reinterpret_cast<const float4*>(in)[i];
        v.x = tf32r(v.x); v.y = tf32r(v.y); v.z = tf32r(v.z); v.w = tf32r(v.w);
        reinterpret_cast<float4*>(out)[i] = v;
    }
}

// ---------------------------------------------------------------------------
// cp.async helpers
// ---------------------------------------------------------------------------
__device__ __forceinline__ void cp16(void* dst, const void* src) {
    uint32_t d = (uint32_t)__cvta_generic_to_shared(dst);
    asm volatile("cp.async.cg.shared.global [%0], [%1], 16;\n" :: "r"(d), "l"(src));
}
#define CP_COMMIT() asm volatile("cp.async.commit_group;\n")
#define CP_WAIT0()  asm volatile("cp.async.wait_group 0;\n")

// ---------------------------------------------------------------------------
// Block-wide all-reduce (blockDim.x == 256)
// ---------------------------------------------------------------------------
__device__ __forceinline__ float blockAllReduceSum(float v) {
    __shared__ float sh[9];
    #pragma unroll
    for (int o = 16; o > 0; o >>= 1) v += __shfl_xor_sync(0xffffffffu, v, o);
    if ((threadIdx.x & 31) == 0) sh[threadIdx.x >> 5] = v;
    __syncthreads();
    if (threadIdx.x < 32) {
        float x = (threadIdx.x < 8) ? sh[threadIdx.x] : 0.f;
        #pragma unroll
        for (int o = 4; o > 0; o >>= 1) x += __shfl_xor_sync(0xffffffffu, x, o);
        if (threadIdx.x == 0) sh[8] = x;
    }
    __syncthreads();
    float r = sh[8];
    __syncthreads();
    return r;
}

// ---------------------------------------------------------------------------
// LayerNorm (tf32-rounded output; only consumed as GEMM A operand)
// ---------------------------------------------------------------------------
__global__ void ln_kernel(const float* __restrict__ x,
                          const float* __restrict__ g1, const float* __restrict__ b1,
                          const float* __restrict__ g2, const float* __restrict__ b2,
                          const int* __restrict__ nvp,
                          float* __restrict__ out)
{
    int row = blockIdx.x;
    const float* gg = g1;
    const float* bb = b1;
    if (g2 != nullptr) {
        if ((row % S_) >= __ldg(nvp)) { gg = g2; bb = b2; }
    }
    int t = threadIdx.x;
    const float4* xr = reinterpret_cast<const float4*>(x + (size_t)row * H_);
    float4 v = xr[t];
    float s = v.x + v.y + v.z + v.w;
    s = blockAllReduceSum(s);
    float mu = s * (1.f / H_);
    float dx = v.x - mu, dy = v.y - mu, dz = v.z - mu, dw = v.w - mu;
    float q = dx * dx + dy * dy + dz * dz + dw * dw;
    q = blockAllReduceSum(q);
    float rs = rsqrtf(q * (1.f / H_) + 1e-5f);
    float4 gv = reinterpret_cast<const float4*>(gg)[t];
    float4 bv = reinterpret_cast<const float4*>(bb)[t];
    float4 o;
    o.x = tf32r(dx * rs * gv.x + bv.x);
    o.y = tf32r(dy * rs * gv.y + bv.y);
    o.z = tf32r(dz * rs * gv.z + bv.z);
    o.w = tf32r(dw * rs * gv.w + bv.w);
    reinterpret_cast<float4*>(out + (size_t)row * H_)[t] = o;
}

// ---------------------------------------------------------------------------
// Tensor-core tf32 GEMM: C = A @ W^T (+epilogue).  128x128x32 tile,
// 256 threads = 8 warps (2 M x 4 N), warp tile 64x32, mma.m16n8k8.tf32.
// MODE 0: +bias, tf32r, permuted store into [B*NH, S, HD]        (Q,K)
// MODE 3: res + acc + bias (opt. per-tile weight select)          (proj/ffn2)
// MODE 4: gelu(acc + bias), tf32-rounded output                   (ffn1)
// MODE 5: +bias, tf32r, TRANSPOSED store into [B*NH, HD, S]       (V)
// ---------------------------------------------------------------------------
#define ASTR 36
#define GEMM_SMEM (2 * 2 * 128 * ASTR * 4)   /* 73728 bytes */

template<int MODE>
__global__ void __launch_bounds__(256)
gemm_tc(const float* __restrict__ A, const float* __restrict__ W,
        const float* __restrict__ bias, const float* __restrict__ res,
        float* __restrict__ C, int M, int N, int K,
        const float* __restrict__ W2, const float* __restrict__ bias2,
        const int* __restrict__ nvp)
{
    extern __shared__ float sm[];
    float* As = sm;                       // [2][128][ASTR]
    float* Bs = sm + 2 * 128 * ASTR;      // [2][128][ASTR]

    const int t    = threadIdx.x;
    const int lane = t & 31;
    const int warp = t >> 5;
    const int wm   = warp & 1;
    const int wn   = warp >> 1;
    const int g    = lane >> 2;
    const int tg   = lane & 3;
    const int bn0  = blockIdx.x * 128;
    const int bm0  = blockIdx.y * 128;

    const float* Wp = W;
    const float* bp = bias;
    if ((MODE == 3 || MODE == 4) && W2 != nullptr) {
        if ((bm0 % S_) >= __ldg(nvp)) { Wp = W2; bp = bias2; }
    }

    float acc[4][4][4];
    #pragma unroll
    for (int i = 0; i < 4; i++)
        #pragma unroll
        for (int j = 0; j < 4; j++)
            #pragma unroll
            for (int c = 0; c < 4; c++) acc[i][j][c] = 0.f;

    const int nk = K >> 5;

    auto load_tile = [&](int buf, int k0) {
        #pragma unroll
        for (int j = 0; j < 4; j++) {
            int i  = t + 256 * j;
            int r  = i >> 3;
            int c4 = (i & 7) * 4;
            cp16(&As[buf * 128 * ASTR + r * ASTR + c4],
                 A  + (size_t)(bm0 + r) * K + k0 + c4);
            cp16(&Bs[buf * 128 * ASTR + r * ASTR + c4],
                 Wp + (size_t)(bn0 + r) * K + k0 + c4);
        }
    };

    load_tile(0, 0);
    CP_COMMIT();

    for (int kt = 0; kt < nk; kt++) {
        CP_WAIT0();
        __syncthreads();
        if (kt + 1 < nk) { load_tile((kt + 1) & 1, (kt + 1) << 5); CP_COMMIT(); }

        const float* Ab = As + (kt & 1) * 128 * ASTR;
        const float* Bb = Bs + (kt & 1) * 128 * ASTR;

        #pragma unroll
        for (int ks = 0; ks < 4; ks++) {
            uint32_t af[4][4];
            #pragma unroll
            for (int mt = 0; mt < 4; mt++) {
                int r = wm * 64 + mt * 16 + g;
                int c = ks * 8 + tg;
                af[mt][0] = __float_as_uint(Ab[r * ASTR + c]);
                af[mt][1] = __float_as_uint(Ab[(r + 8) * ASTR + c]);
                af[mt][2] = __float_as_uint(Ab[r * ASTR + c + 4]);
                af[mt][3] = __float_as_uint(Ab[(r + 8) * ASTR + c + 4]);
            }
            uint32_t bf[4][2];
            #pragma unroll
            for (int nt = 0; nt < 4; nt++) {
                int n = wn * 32 + nt * 8 + g;
                int c = ks * 8 + tg;
                bf[nt][0] = __float_as_uint(Bb[n * ASTR + c]);
                bf[nt][1] = __float_as_uint(Bb[n * ASTR + c + 4]);
            }
            #pragma unroll
            for (int mt = 0; mt < 4; mt++)
                #pragma unroll
                for (int nt = 0; nt < 4; nt++) {
                    asm volatile(
                        "mma.sync.aligned.m16n8k8.row.col.f32.tf32.tf32.f32 "
                        "{%0,%1,%2,%3}, {%4,%5,%6,%7}, {%8,%9}, {%0,%1,%2,%3};\n"
                        : "+f"(acc[mt][nt][0]), "+f"(acc[mt][nt][1]),
                          "+f"(acc[mt][nt][2]), "+f"(acc[mt][nt][3])
                        : "r"(af[mt][0]), "r"(af[mt][1]), "r"(af[mt][2]), "r"(af[mt][3]),
                          "r"(bf[nt][0]), "r"(bf[nt][1]));
                }
        }
        __syncthreads();
    }

    // ---- epilogue ----
    #pragma unroll
    for (int mt = 0; mt < 4; mt++) {
        #pragma unroll
        for (int nt = 0; nt < 4; nt++) {
            int m = bm0 + wm * 64 + mt * 16 + g;
            int n = bn0 + wn * 32 + nt * 8 + tg * 2;
            float2 bb2 = *reinterpret_cast<const float2*>(bp + n);
            #pragma unroll
            for (int h = 0; h < 2; h++) {
                int mr = m + h * 8;
                float vx = acc[mt][nt][h * 2 + 0] + bb2.x;
                float vy = acc[mt][nt][h * 2 + 1] + bb2.y;
                if (MODE == 0) {
                    int b = mr / S_, s = mr % S_;
                    int hh = n >> 7, d = n & 127;
                    *reinterpret_cast<float2*>(
                        C + ((size_t)(b * NH_ + hh) * S_ + s) * HD_ + d) =
                        make_float2(tf32r(vx), tf32r(vy));
                } else if (MODE == 3) {
                    size_t idx = (size_t)mr * N + n;
                    float2 r2 = *reinterpret_cast<const float2*>(res + idx);
                    *reinterpret_cast<float2*>(C + idx) =
                        make_float2(r2.x + vx, r2.y + vy);
                } else if (MODE == 4) {
                    float gx = 0.5f * vx * (1.f + erff(vx * 0.7071067811865475f));
                    float gy = 0.5f * vy * (1.f + erff(vy * 0.7071067811865475f));
                    *reinterpret_cast<float2*>(C + (size_t)mr * N + n) =
                        make_float2(tf32r(gx), tf32r(gy));
                } else {   // MODE 5: V transposed -> [B*NH, HD, S]
                    int b = mr / S_, s = mr % S_;
                    int hh = n >> 7, d = n & 127;
                    float* dst = C + ((size_t)(b * NH_ + hh) * HD_ + d) * S_ + s;
                    dst[0]  = tf32r(vx);
                    dst[S_] = tf32r(vy);
                }
            }
        }
    }
}

// ---------------------------------------------------------------------------
// Tensor-core flash attention. Grid: (S_/128, B_*NH_), 256 threads, occ 1.
// Q,K in [B*NH, S, HD] (tf32); Vt in [B*NH, HD, S] (tf32).
// O -> [B, S, H], tf32-rounded.
// smem: As/Bs 2x[2][128][36] + Ps[128][132] + red[8][128] = 145408 B.
// ---------------------------------------------------------------------------
#define FTC_SMEM ((4 * 128 * ASTR + 128 * 132 + 8 * 128) * 4)

__global__ void __launch_bounds__(256, 1)
flash_tc(const float* __restrict__ Q, const float* __restrict__ K,
         const float* __restrict__ Vt, const int* __restrict__ mask,
         float* __restrict__ O)
{
    extern __shared__ float sm[];
    float* As   = sm;                        // [2][128][36]  (Q chunks)
    float* Bs   = sm + 2 * 128 * ASTR;       // [2][128][36]  (K / Vt chunks)
    float* Ps   = sm + 4 * 128 * ASTR;       // [128][132]
    float* redm = Ps + 128 * 132;            // [4][128]
    float* reds = redm + 4 * 128;            // [4][128]

    const int t    = threadIdx.x;
    const int lane = t & 31;
    const int warp = t >> 5;
    const int wm   = warp & 1;
    const int wn   = warp >> 1;
    const int g    = lane >> 2;
    const int tg   = lane & 3;

    const int bm0 = blockIdx.x * 128;
    const int z   = blockIdx.y;
    const int b   = z >> 3, hhead = z & 7;

    const float* Qp = Q  + (size_t)z * S_ * HD_;
    const float* Kp = K  + (size_t)z * S_ * HD_;
    const float* Vp = Vt + (size_t)z * HD_ * S_;
    const int*   Mp = mask + (size_t)b * S_ * S_;

    const float SC = 0.08838834764831845f;

    float o_acc[4][4][4];
    float m_i[4][2], l_i[4][2];
    #pragma unroll
    for (int mt = 0; mt < 4; mt++) {
        #pragma unroll
        for (int h = 0; h < 2; h++) { m_i[mt][h] = -INFINITY; l_i[mt][h] = 0.f; }
        #pragma unroll
        for (int nt = 0; nt < 4; nt++)
            #pragma unroll
            for (int c = 0; c < 4; c++) o_acc[mt][nt][c] = 0.f;
    }

    auto load_qk = [&](int buf, int bn0, int k0) {
        #pragma unroll
        for (int j = 0; j < 4; j++) {
            int i  = t + 256 * j;
            int r  = i >> 3;
            int c4 = (i & 7) * 4;
            cp16(&As[buf * 128 * ASTR + r * ASTR + c4],
                 Qp + (size_t)(bm0 + r) * HD_ + k0 + c4);
            cp16(&Bs[buf * 128 * ASTR + r * ASTR + c4],
                 Kp + (size_t)(bn0 + r) * HD_ + k0 + c4);
        }
    };
    auto load_v = [&](int buf, int bn0, int k0) {
        #pragma unroll
        for (int j = 0; j < 4; j++) {
            int i  = t + 256 * j;
            int r  = i >> 3;               // hd row
            int c4 = (i & 7) * 4;          // kv col within chunk
            cp16(&Bs[buf * 128 * ASTR + r * ASTR + c4],
                 Vp + (size_t)r * S_ + bn0 + k0 + c4);
        }
    };

    for (int kt = 0; kt < S_ / 128; kt++) {
        const int bn0 = kt * 128;

        // ================= QK^T =================
        float s_acc[4][4][4];
        #pragma unroll
        for (int mt = 0; mt < 4; mt++)
            #pragma unroll
            for (int nt = 0; nt < 4; nt++)
                #pragma unroll
                for (int c = 0; c < 4; c++) s_acc[mt][nt][c] = 0.f;

        load_qk(0, bn0, 0);
        CP_COMMIT();
        #pragma unroll
        for (int kc = 0; kc < 4; kc++) {
            CP_WAIT0();
            __syncthreads();
            if (kc < 3) { load_qk((kc + 1) & 1, bn0, (kc + 1) * 32); CP_COMMIT(); }
            const float* Ab = As + (kc & 1) * 128 * ASTR;
            const float* Bb = Bs + (kc & 1) * 128 * ASTR;
            #pragma unroll
            for (int ks = 0; ks < 4; ks++) {
                uint32_t af[4][4];
                #pragma unroll
                for (int mt = 0; mt < 4; mt++) {
                    int r = wm * 64 + mt * 16 + g;
                    int c = ks * 8 + tg;
                    af[mt][0] = __float_as_uint(Ab[r * ASTR + c]);
                    af[mt][1] = __float_as_uint(Ab[(r + 8) * ASTR + c]);
                    af[mt][2] = __float_as_uint(Ab[r * ASTR + c + 4]);
                    af[mt][3] = __float_as_uint(Ab[(r + 8) * ASTR + c + 4]);
                }
                uint32_t bf[4][2];
                #pragma unroll
                for (int nt = 0; nt < 4; nt++) {
                    int n = wn * 32 + nt * 8 + g;
                    int c = ks * 8 + tg;
                    bf[nt][0] = __float_as_uint(Bb[n * ASTR + c]);
                    bf[nt][1] = __float_as_uint(Bb[n * ASTR + c + 4]);
                }
                #pragma unroll
                for (int mt = 0; mt < 4; mt++)
                    #pragma unroll
                    for (int nt = 0; nt < 4; nt++) {
                        asm volatile(
                            "mma.sync.aligned.m16n8k8.row.col.f32.tf32.tf32.f32 "
                            "{%0,%1,%2,%3}, {%4,%5,%6,%7}, {%8,%9}, {%0,%1,%2,%3};\n"
                            : "+f"(s_acc[mt][nt][0]), "+f"(s_acc[mt][nt][1]),
                              "+f"(s_acc[mt][nt][2]), "+f"(s_acc[mt][nt][3])
                            : "r"(af[mt][0]), "r"(af[mt][1]), "r"(af[mt][2]), "r"(af[mt][3]),
                              "r"(bf[nt][0]), "r"(bf[nt][1]));
                    }
            }
            __syncthreads();
        }

        // ================= online softmax =================
        float rmax[4][2];
        #pragma unroll
        for (int mt = 0; mt < 4; mt++) {
            #pragma unroll
            for (int h = 0; h < 2; h++) {
                int row = bm0 + wm * 64 + mt * 16 + g + h * 8;
                const int* mrow = Mp + (size_t)row * S_ + bn0;
                float mx = -INFINITY;
                #pragma unroll
                for (int nt = 0; nt < 4; nt++) {
                    int2 mk = *reinterpret_cast<const int2*>(mrow + wn * 32 + nt * 8 + tg * 2);
                    float vx = (mk.x > 0) ? s_acc[mt][nt][h * 2 + 0] * SC : -INFINITY;
                    float vy = (mk.y > 0) ? s_acc[mt][nt][h * 2 + 1] * SC : -INFINITY;
                    s_acc[mt][nt][h * 2 + 0] = vx;
                    s_acc[mt][nt][h * 2 + 1] = vy;
                    mx = fmaxf(mx, fmaxf(vx, vy));
                }
                mx = fmaxf(mx, __shfl_xor_sync(0xffffffffu, mx, 1));
                mx = fmaxf(mx, __shfl_xor_sync(0xffffffffu, mx, 2));
                rmax[mt][h] = mx;
            }
        }
        if (tg == 0) {
            #pragma unroll
            for (int mt = 0; mt < 4; mt++)
                #pragma unroll
                for (int h = 0; h < 2; h++)
                    redm[wn * 128 + wm * 64 + mt * 16 + g + h * 8] = rmax[mt][h];
        }
        __syncthreads();

        float corr_s[4][2];
        #pragma unroll
        for (int mt = 0; mt < 4; mt++) {
            #pragma unroll
            for (int h = 0; h < 2; h++) {
                int rl = wm * 64 + mt * 16 + g + h * 8;
                float tm = fmaxf(fmaxf(redm[rl], redm[128 + rl]),
                                 fmaxf(redm[256 + rl], redm[384 + rl]));
                float mo = m_i[mt][h];
                float mnew = fmaxf(mo, tm);
                float corr = (mo == -INFINITY) ? 0.f : __expf(mo - mnew);
                float s = 0.f;
                #pragma unroll
                for (int nt = 0; nt < 4; nt++) {
                    float px = tf32r(__expf(s_acc[mt][nt][h * 2 + 0] - mnew));
                    float py = tf32r(__expf(s_acc[mt][nt][h * 2 + 1] - mnew));
                    s += px + py;
                    *reinterpret_cast<float2*>(&Ps[rl * 132 + wn * 32 + nt * 8 + tg * 2]) =
                        make_float2(px, py);
                }
                s += __shfl_xor_sync(0xffffffffu, s, 1);
                s += __shfl_xor_sync(0xffffffffu, s, 2);
                if (tg == 0) reds[wn * 128 + rl] = s;
                m_i[mt][h]  = mnew;
                corr_s[mt][h] = corr;
                #pragma unroll
                for (int nt = 0; nt < 4; nt++) {
                    o_acc[mt][nt][h * 2 + 0] *= corr;
                    o_acc[mt][nt][h * 2 + 1] *= corr;
                }
            }
        }
        __syncthreads();
        #pragma unroll
        for (int mt = 0; mt < 4; mt++)
            #pragma unroll
            for (int h = 0; h < 2; h++) {
                int rl = wm * 64 + mt * 16 + g + h * 8;
                float ts = reds[rl] + reds[128 + rl] + reds[256 + rl] + reds[384 + rl];
                l_i[mt][h] = l_i[mt][h] * corr_s[mt][h] + ts;
            }

        // ================= O += P @ V =================
        load_v(0, bn0, 0);
        CP_COMMIT();
        #pragma unroll
        for (int kc = 0; kc < 4; kc++) {
            CP_WAIT0();
            __syncthreads();
            if (kc < 3) { load_v((kc + 1) & 1, bn0, (kc + 1) * 32); CP_COMMIT(); }
            const float* Bb = Bs + (kc & 1) * 128 * ASTR;
            #pragma unroll
            for (int ks = 0; ks < 4; ks++) {
                uint32_t af[4][4];
                #pragma unroll
                for (int mt = 0; mt < 4; mt++) {
                    int r = wm * 64 + mt * 16 + g;
                    int c = kc * 32 + ks * 8 + tg;
                    af[mt][0] = __float_as_uint(Ps[r * 132 + c]);
                    af[mt][1] = __float_as_uint(Ps[(r + 8) * 132 + c]);
                    af[mt][2] = __float_as_uint(Ps[r * 132 + c + 4]);
                    af[mt][3] = __float_as_uint(Ps[(r + 8) * 132 + c + 4]);
                }
                uint32_t bf[4][2];
                #pragma unroll
                for (int nt = 0; nt < 4; nt++) {
                    int n = wn * 32 + nt * 8 + g;
                    int c = ks * 8 + tg;
                    bf[nt][0] = __float_as_uint(Bb[n * ASTR + c]);
                    bf[nt][1] = __float_as_uint(Bb[n * ASTR + c + 4]);
                }
                #pragma unroll
                for (int mt = 0; mt < 4; mt++)
                    #pragma unroll
                    for (int nt = 0; nt < 4; nt++) {
                        asm volatile(
                            "mma.sync.aligned.m16n8k8.row.col.f32.tf32.tf32.f32 "
                            "{%0,%1,%2,%3}, {%4,%5,%6,%7}, {%8,%9}, {%0,%1,%2,%3};\n"
                            : "+f"(o_acc[mt][nt][0]), "+f"(o_acc[mt][nt][1]),
                              "+f"(o_acc[mt][nt][2]), "+f"(o_acc[mt][nt][3])
                            : "r"(af[mt][0]), "r"(af[mt][1]), "r"(af[mt][2]), "r"(af[mt][3]),
                              "r"(bf[nt][0]), "r"(bf[nt][1]));
                    }
            }
            __syncthreads();
        }
    }

    // ---- epilogue: normalize and store ----
    #pragma unroll
    for (int mt = 0; mt < 4; mt++) {
        #pragma unroll
        for (int h = 0; h < 2; h++) {
            int rl = wm * 64 + mt * 16 + g + h * 8;
            float inv = 1.f / l_i[mt][h];
            float* orow = O + ((size_t)b * S_ + (bm0 + rl)) * H_ + hhead * HD_;
            #pragma unroll
            for (int nt = 0; nt < 4; nt++) {
                int c = wn * 32 + nt * 8 + tg * 2;
                *reinterpret_cast<float2*>(orow + c) =
                    make_float2(tf32r(o_acc[mt][nt][h * 2 + 0] * inv),
                                tf32r(o_acc[mt][nt][h * 2 + 1] * inv));
            }
        }
    }
}

// ---------------------------------------------------------------------------
// Host driver
// ---------------------------------------------------------------------------
extern "C" void kernel_launch(void* const* d_in, const int* in_sizes, int n_in,
                              void* d_out, int out_size)
{
    const float* fused  = (const float*)d_in[0];
    const int*   mask   = (const int*)  d_in[1];
    const int*   nvp    = (const int*)  d_in[2];
    const float* ln1_g  = (const float*)d_in[4];
    const float* ln1_b  = (const float*)d_in[5];
    const float* wq     = (const float*)d_in[6];
    const float* bq     = (const float*)d_in[7];
    const float* wk     = (const float*)d_in[8];
    const float* bk     = (const float*)d_in[9];
    const float* wv     = (const float*)d_in[10];
    const float* bv     = (const float*)d_in[11];
    const float* wm     = (const float*)d_in[12];
    const float* bmp    = (const float*)d_in[13];
    const float* ln2v_g = (const float*)d_in[14];
    const float* ln2v_b = (const float*)d_in[15];
    const float* fv1_w  = (const float*)d_in[16];
    const float* fv1_b  = (const float*)d_in[17];
    const float* fv2_w  = (const float*)d_in[18];
    const float* fv2_b  = (const float*)d_in[19];
    const float* ln2t_g = (const float*)d_in[20];
    const float* ln2t_b = (const float*)d_in[21];
    const float* ft1_w  = (const float*)d_in[22];
    const float* ft1_b  = (const float*)d_in[23];
    const float* ft2_w  = (const float*)d_in[24];
    const float* ft2_b  = (const float*)d_in[25];

    float* base = nullptr;
    cudaGetSymbolAddress((void**)&base, g_buf);
    float* xn  = base;
    float* qb  = base + 1 * XSZ;
    float* kb  = base + 2 * XSZ;
    float* vb  = base + 3 * XSZ;   // Vt layout [B*NH, HD, S]
    float* rb  = base + 4 * XSZ;
    float* xb  = base + 5 * XSZ;
    float* hb  = base + 6 * XSZ;
    float* wt  = base + 6 * XSZ + HSZ;
    float* wq_t  = wt;
    float* wk_t  = wt + 1 * WSQ;
    float* wv_t  = wt + 2 * WSQ;
    float* wm_t  = wt + 3 * WSQ;
    float* fv1_t = wt + 4 * WSQ;
    float* ft1_t = fv1_t + WSF;
    float* fv2_t = ft1_t + WSF;
    float* ft2_t = fv2_t + WSF;

    cudaFuncSetAttribute(flash_tc,
                         cudaFuncAttributeMaxDynamicSharedMemorySize, FTC_SMEM);
    cudaFuncSetAttribute(gemm_tc<0>,
                         cudaFuncAttributeMaxDynamicSharedMemorySize, GEMM_SMEM);
    cudaFuncSetAttribute(gemm_tc<3>,
                         cudaFuncAttributeMaxDynamicSharedMemorySize, GEMM_SMEM);
    cudaFuncSetAttribute(gemm_tc<4>,
                         cudaFuncAttributeMaxDynamicSharedMemorySize, GEMM_SMEM);
    cudaFuncSetAttribute(gemm_tc<5>,
                         cudaFuncAttributeMaxDynamicSharedMemorySize, GEMM_SMEM);

    // ---- one-time tf32 weight prep ----
    {
        int nq4 = (int)(WSQ / 4), nf4 = (int)(WSF / 4);
        int tq = 256, gq = (nq4 + tq - 1) / tq, gf = (nf4 + tq - 1) / tq;
        round_tf32_k<<<gq, tq>>>(wq, wq_t, nq4);
        round_tf32_k<<<gq, tq>>>(wk, wk_t, nq4);
        round_tf32_k<<<gq, tq>>>(wv, wv_t, nq4);
        round_tf32_k<<<gq, tq>>>(wm, wm_t, nq4);
        round_tf32_k<<<gf, tq>>>(fv1_w, fv1_t, nf4);
        round_tf32_k<<<gf, tq>>>(ft1_w, ft1_t, nf4);
        round_tf32_k<<<gf, tq>>>(fv2_w, fv2_t, nf4);
        round_tf32_k<<<gf, tq>>>(ft2_w, ft2_t, nf4);
    }

    dim3 thr(256);
    dim3 gProj(H_ / 128, M_ / 128);            // (8, 48)
    dim3 gF1(FF_ / 128, M_ / 128);             // (32, 48)
    dim3 gFl(S_ / 128, B_ * NH_);              // (12, 32)

    const float* xc = fused;
    for (int layer = 0; layer < 6; layer++) {
        float* xnext = (layer == 5) ? (float*)d_out : xb;

        // ---- attention block ----
        ln_kernel<<<M_, thr>>>(xc, ln1_g, ln1_b, nullptr, nullptr, nullptr, xn);
        gemm_tc<0><<<gProj, thr, GEMM_SMEM>>>(xn, wq_t, bq, nullptr, qb, M_, H_, H_, nullptr, nullptr, nullptr);
        gemm_tc<0><<<gProj, thr, GEMM_SMEM>>>(xn, wk_t, bk, nullptr, kb, M_, H_, H_, nullptr, nullptr, nullptr);
        gemm_tc<5><<<gProj, thr, GEMM_SMEM>>>(xn, wv_t, bv, nullptr, vb, M_, H_, H_, nullptr, nullptr, nullptr);
        flash_tc<<<gFl, thr, FTC_SMEM>>>(qb, kb, vb, mask, xn);
        gemm_tc<3><<<gProj, thr, GEMM_SMEM>>>(xn, wm_t, bmp, xc, rb, M_, H_, H_, nullptr, nullptr, nullptr);

        // ---- split FFN block ----
        ln_kernel<<<M_, thr>>>(rb, ln2v_g, ln2v_b, ln2t_g, ln2t_b, nvp, xn);
        gemm_tc<4><<<gF1, thr, GEMM_SMEM>>>(xn, fv1_t, fv1_b, nullptr, hb, M_, FF_, H_, ft1_t, ft1_b, nvp);
        gemm_tc<3><<<gProj, thr, GEMM_SMEM>>>(hb, fv2_t, fv2_b, rb, xnext, M_, H_, FF_, ft2_t, ft2_b, nvp);

        xc = xnext;
    }
}

// round 7
// speedup vs baseline: 3.1099x; 1.0018x over previous
#include <cuda_runtime.h>
#include <math.h>
#include <stdint.h>

// ---------------------------------------------------------------------------
// Problem constants (fixed by setup_inputs)
// ---------------------------------------------------------------------------
#define B_   4
#define S_   1536
#define H_   1024
#define NH_  8
#define HD_  128
#define FF_  4096
#define M_   (B_ * S_)          /* 6144 rows total */

#define XSZ  6291456ull         /* M_ * H_ floats */
#define HSZ  25165824ull        /* M_ * FF_ floats */
#define WSQ  ((size_t)H_ * H_)
#define WSF  ((size_t)FF_ * H_)

__device__ float g_buf[6 * XSZ + HSZ + 4 * WSQ + 4 * WSF];

// ---------------------------------------------------------------------------
// tf32 helpers
// ---------------------------------------------------------------------------
__device__ __forceinline__ float tf32r(float x) {
    uint32_t u;
    asm("cvt.rna.tf32.f32 %0, %1;" : "=r"(u) : "f"(x));
    return __uint_as_float(u);
}

__global__ void round_tf32_k(const float* __restrict__ in, float* __restrict__ out, int n4)
{
    int i = blockIdx.x * blockDim.x + threadIdx.x;
    if (i < n4) {
        float4 v = reinterpret_cast<const float4*>(in)[i];
        v.x = tf32r(v.x); v.y = tf32r(v.y); v.z = tf32r(v.z); v.w = tf32r(v.w);
        reinterpret_cast<float4*>(out)[i] = v;
    }
}

// ---------------------------------------------------------------------------
// cp.async helpers
// ---------------------------------------------------------------------------
__device__ __forceinline__ void cp16(void* dst, const void* src) {
    uint32_t d = (uint32_t)__cvta_generic_to_shared(dst);
    asm volatile("cp.async.cg.shared.global [%0], [%1], 16;\n" :: "r"(d), "l"(src));
}
#define CP_COMMIT() asm volatile("cp.async.commit_group;\n")
#define CP_WAIT0()  asm volatile("cp.async.wait_group 0;\n")

// ---------------------------------------------------------------------------
// Block-wide all-reduce (blockDim.x == 256)
// ---------------------------------------------------------------------------
__device__ __forceinline__ float blockAllReduceSum(float v) {
    __shared__ float sh[9];
    #pragma unroll
    for (int o = 16; o > 0; o >>= 1) v += __shfl_xor_sync(0xffffffffu, v, o);
    if ((threadIdx.x & 31) == 0) sh[threadIdx.x >> 5] = v;
    __syncthreads();
    if (threadIdx.x < 32) {
        float x = (threadIdx.x < 8) ? sh[threadIdx.x] : 0.f;
        #pragma unroll
        for (int o = 4; o > 0; o >>= 1) x += __shfl_xor_sync(0xffffffffu, x, o);
        if (threadIdx.x == 0) sh[8] = x;
    }
    __syncthreads();
    float r = sh[8];
    __syncthreads();
    return r;
}

// ---------------------------------------------------------------------------
// LayerNorm (tf32-rounded output; only consumed as GEMM A operand)
// ---------------------------------------------------------------------------
__global__ void ln_kernel(const float* __restrict__ x,
                          const float* __restrict__ g1, const float* __restrict__ b1,
                          const float* __restrict__ g2, const float* __restrict__ b2,
                          const int* __restrict__ nvp,
                          float* __restrict__ out)
{
    int row = blockIdx.x;
    const float* gg = g1;
    const float* bb = b1;
    if (g2 != nullptr) {
        if ((row % S_) >= __ldg(nvp)) { gg = g2; bb = b2; }
    }
    int t = threadIdx.x;
    const float4* xr = reinterpret_cast<const float4*>(x + (size_t)row * H_);
    float4 v = xr[t];
    float s = v.x + v.y + v.z + v.w;
    s = blockAllReduceSum(s);
    float mu = s * (1.f / H_);
    float dx = v.x - mu, dy = v.y - mu, dz = v.z - mu, dw = v.w - mu;
    float q = dx * dx + dy * dy + dz * dz + dw * dw;
    q = blockAllReduceSum(q);
    float rs = rsqrtf(q * (1.f / H_) + 1e-5f);
    float4 gv = reinterpret_cast<const float4*>(gg)[t];
    float4 bv = reinterpret_cast<const float4*>(bb)[t];
    float4 o;
    o.x = tf32r(dx * rs * gv.x + bv.x);
    o.y = tf32r(dy * rs * gv.y + bv.y);
    o.z = tf32r(dz * rs * gv.z + bv.z);
    o.w = tf32r(dw * rs * gv.w + bv.w);
    reinterpret_cast<float4*>(out + (size_t)row * H_)[t] = o;
}

// ---------------------------------------------------------------------------
// Tensor-core tf32 GEMM: C = A @ W^T (+epilogue).  128x128x32 tile,
// 256 threads = 8 warps (2 M x 4 N), warp tile 64x32, mma.m16n8k8.tf32.
// MODE 0: +bias, tf32r, permuted store into [B*NH, S, HD]        (Q,K)
// MODE 3: res + acc + bias (opt. per-tile weight select)          (proj/ffn2)
// MODE 4: gelu(acc + bias), tf32-rounded output                   (ffn1)
// MODE 5: +bias, tf32r, TRANSPOSED store into [B*NH, HD, S]       (V)
// ---------------------------------------------------------------------------
#define ASTR 36
#define GEMM_SMEM (2 * 2 * 128 * ASTR * 4)   /* 73728 bytes */

template<int MODE>
__global__ void __launch_bounds__(256)
gemm_tc(const float* __restrict__ A, const float* __restrict__ W,
        const float* __restrict__ bias, const float* __restrict__ res,
        float* __restrict__ C, int M, int N, int K,
        const float* __restrict__ W2, const float* __restrict__ bias2,
        const int* __restrict__ nvp)
{
    extern __shared__ float sm[];
    float* As = sm;                       // [2][128][ASTR]
    float* Bs = sm + 2 * 128 * ASTR;      // [2][128][ASTR]

    const int t    = threadIdx.x;
    const int lane = t & 31;
    const int warp = t >> 5;
    const int wm   = warp & 1;
    const int wn   = warp >> 1;
    const int g    = lane >> 2;
    const int tg   = lane & 3;
    const int bn0  = blockIdx.x * 128;
    const int bm0  = blockIdx.y * 128;

    const float* Wp = W;
    const float* bp = bias;
    if ((MODE == 3 || MODE == 4) && W2 != nullptr) {
        if ((bm0 % S_) >= __ldg(nvp)) { Wp = W2; bp = bias2; }
    }

    float acc[4][4][4];
    #pragma unroll
    for (int i = 0; i < 4; i++)
        #pragma unroll
        for (int j = 0; j < 4; j++)
            #pragma unroll
            for (int c = 0; c < 4; c++) acc[i][j][c] = 0.f;

    const int nk = K >> 5;

    auto load_tile = [&](int buf, int k0) {
        #pragma unroll
        for (int j = 0; j < 4; j++) {
            int i  = t + 256 * j;
            int r  = i >> 3;
            int c4 = (i & 7) * 4;
            cp16(&As[buf * 128 * ASTR + r * ASTR + c4],
                 A  + (size_t)(bm0 + r) * K + k0 + c4);
            cp16(&Bs[buf * 128 * ASTR + r * ASTR + c4],
                 Wp + (size_t)(bn0 + r) * K + k0 + c4);
        }
    };

    load_tile(0, 0);
    CP_COMMIT();

    for (int kt = 0; kt < nk; kt++) {
        CP_WAIT0();
        __syncthreads();
        if (kt + 1 < nk) { load_tile((kt + 1) & 1, (kt + 1) << 5); CP_COMMIT(); }

        const float* Ab = As + (kt & 1) * 128 * ASTR;
        const float* Bb = Bs + (kt & 1) * 128 * ASTR;

        #pragma unroll
        for (int ks = 0; ks < 4; ks++) {
            uint32_t af[4][4];
            #pragma unroll
            for (int mt = 0; mt < 4; mt++) {
                int r = wm * 64 + mt * 16 + g;
                int c = ks * 8 + tg;
                af[mt][0] = __float_as_uint(Ab[r * ASTR + c]);
                af[mt][1] = __float_as_uint(Ab[(r + 8) * ASTR + c]);
                af[mt][2] = __float_as_uint(Ab[r * ASTR + c + 4]);
                af[mt][3] = __float_as_uint(Ab[(r + 8) * ASTR + c + 4]);
            }
            uint32_t bf[4][2];
            #pragma unroll
            for (int nt = 0; nt < 4; nt++) {
                int n = wn * 32 + nt * 8 + g;
                int c = ks * 8 + tg;
                bf[nt][0] = __float_as_uint(Bb[n * ASTR + c]);
                bf[nt][1] = __float_as_uint(Bb[n * ASTR + c + 4]);
            }
            #pragma unroll
            for (int mt = 0; mt < 4; mt++)
                #pragma unroll
                for (int nt = 0; nt < 4; nt++) {
                    asm volatile(
                        "mma.sync.aligned.m16n8k8.row.col.f32.tf32.tf32.f32 "
                        "{%0,%1,%2,%3}, {%4,%5,%6,%7}, {%8,%9}, {%0,%1,%2,%3};\n"
                        : "+f"(acc[mt][nt][0]), "+f"(acc[mt][nt][1]),
                          "+f"(acc[mt][nt][2]), "+f"(acc[mt][nt][3])
                        : "r"(af[mt][0]), "r"(af[mt][1]), "r"(af[mt][2]), "r"(af[mt][3]),
                          "r"(bf[nt][0]), "r"(bf[nt][1]));
                }
        }
        __syncthreads();
    }

    // ---- epilogue ----
    #pragma unroll
    for (int mt = 0; mt < 4; mt++) {
        #pragma unroll
        for (int nt = 0; nt < 4; nt++) {
            int m = bm0 + wm * 64 + mt * 16 + g;
            int n = bn0 + wn * 32 + nt * 8 + tg * 2;
            float2 bb2 = *reinterpret_cast<const float2*>(bp + n);
            #pragma unroll
            for (int h = 0; h < 2; h++) {
                int mr = m + h * 8;
                float vx = acc[mt][nt][h * 2 + 0] + bb2.x;
                float vy = acc[mt][nt][h * 2 + 1] + bb2.y;
                if (MODE == 0) {
                    int b = mr / S_, s = mr % S_;
                    int hh = n >> 7, d = n & 127;
                    *reinterpret_cast<float2*>(
                        C + ((size_t)(b * NH_ + hh) * S_ + s) * HD_ + d) =
                        make_float2(tf32r(vx), tf32r(vy));
                } else if (MODE == 3) {
                    size_t idx = (size_t)mr * N + n;
                    float2 r2 = *reinterpret_cast<const float2*>(res + idx);
                    *reinterpret_cast<float2*>(C + idx) =
                        make_float2(r2.x + vx, r2.y + vy);
                } else if (MODE == 4) {
                    float gx = 0.5f * vx * (1.f + erff(vx * 0.7071067811865475f));
                    float gy = 0.5f * vy * (1.f + erff(vy * 0.7071067811865475f));
                    *reinterpret_cast<float2*>(C + (size_t)mr * N + n) =
                        make_float2(tf32r(gx), tf32r(gy));
                } else {   // MODE 5: V transposed -> [B*NH, HD, S]
                    int b = mr / S_, s = mr % S_;
                    int hh = n >> 7, d = n & 127;
                    float* dst = C + ((size_t)(b * NH_ + hh) * HD_ + d) * S_ + s;
                    dst[0]  = tf32r(vx);
                    dst[S_] = tf32r(vy);
                }
            }
        }
    }
}

// ---------------------------------------------------------------------------
// Tensor-core flash attention. Grid: (S_/128, B_*NH_), 256 threads, occ 1.
// Q,K in [B*NH, S, HD] (tf32); Vt in [B*NH, HD, S] (tf32).
// O -> [B, S, H], tf32-rounded.
// smem: As/Bs 2x[2][128][36] + Ps[128][132] + red[8][128] = 145408 B.
// ---------------------------------------------------------------------------
#define FTC_SMEM ((4 * 128 * ASTR + 128 * 132 + 8 * 128) * 4)

__global__ void __launch_bounds__(256, 1)
flash_tc(const float* __restrict__ Q, const float* __restrict__ K,
         const float* __restrict__ Vt, const int* __restrict__ mask,
         float* __restrict__ O)
{
    extern __shared__ float sm[];
    float* As   = sm;                        // [2][128][36]  (Q chunks)
    float* Bs   = sm + 2 * 128 * ASTR;       // [2][128][36]  (K / Vt chunks)
    float* Ps   = sm + 4 * 128 * ASTR;       // [128][132]
    float* redm = Ps + 128 * 132;            // [4][128]
    float* reds = redm + 4 * 128;            // [4][128]

    const int t    = threadIdx.x;
    const int lane = t & 31;
    const int warp = t >> 5;
    const int wm   = warp & 1;
    const int wn   = warp >> 1;
    const int g    = lane >> 2;
    const int tg   = lane & 3;

    const int bm0 = blockIdx.x * 128;
    const int z   = blockIdx.y;
    const int b   = z >> 3, hhead = z & 7;

    const float* Qp = Q  + (size_t)z * S_ * HD_;
    const float* Kp = K  + (size_t)z * S_ * HD_;
    const float* Vp = Vt + (size_t)z * HD_ * S_;
    const int*   Mp = mask + (size_t)b * S_ * S_;

    const float SC = 0.08838834764831845f;

    float o_acc[4][4][4];
    float m_i[4][2], l_i[4][2];
    #pragma unroll
    for (int mt = 0; mt < 4; mt++) {
        #pragma unroll
        for (int h = 0; h < 2; h++) { m_i[mt][h] = -INFINITY; l_i[mt][h] = 0.f; }
        #pragma unroll
        for (int nt = 0; nt < 4; nt++)
            #pragma unroll
            for (int c = 0; c < 4; c++) o_acc[mt][nt][c] = 0.f;
    }

    auto load_qk = [&](int buf, int bn0, int k0) {
        #pragma unroll
        for (int j = 0; j < 4; j++) {
            int i  = t + 256 * j;
            int r  = i >> 3;
            int c4 = (i & 7) * 4;
            cp16(&As[buf * 128 * ASTR + r * ASTR + c4],
                 Qp + (size_t)(bm0 + r) * HD_ + k0 + c4);
            cp16(&Bs[buf * 128 * ASTR + r * ASTR + c4],
                 Kp + (size_t)(bn0 + r) * HD_ + k0 + c4);
        }
    };
    auto load_v = [&](int buf, int bn0, int k0) {
        #pragma unroll
        for (int j = 0; j < 4; j++) {
            int i  = t + 256 * j;
            int r  = i >> 3;               // hd row
            int c4 = (i & 7) * 4;          // kv col within chunk
            cp16(&Bs[buf * 128 * ASTR + r * ASTR + c4],
                 Vp + (size_t)r * S_ + bn0 + k0 + c4);
        }
    };

    for (int kt = 0; kt < S_ / 128; kt++) {
        const int bn0 = kt * 128;

        // ================= QK^T =================
        float s_acc[4][4][4];
        #pragma unroll
        for (int mt = 0; mt < 4; mt++)
            #pragma unroll
            for (int nt = 0; nt < 4; nt++)
                #pragma unroll
                for (int c = 0; c < 4; c++) s_acc[mt][nt][c] = 0.f;

        load_qk(0, bn0, 0);
        CP_COMMIT();
        #pragma unroll
        for (int kc = 0; kc < 4; kc++) {
            CP_WAIT0();
            __syncthreads();
            if (kc < 3) { load_qk((kc + 1) & 1, bn0, (kc + 1) * 32); CP_COMMIT(); }
            const float* Ab = As + (kc & 1) * 128 * ASTR;
            const float* Bb = Bs + (kc & 1) * 128 * ASTR;
            #pragma unroll
            for (int ks = 0; ks < 4; ks++) {
                uint32_t af[4][4];
                #pragma unroll
                for (int mt = 0; mt < 4; mt++) {
                    int r = wm * 64 + mt * 16 + g;
                    int c = ks * 8 + tg;
                    af[mt][0] = __float_as_uint(Ab[r * ASTR + c]);
                    af[mt][1] = __float_as_uint(Ab[(r + 8) * ASTR + c]);
                    af[mt][2] = __float_as_uint(Ab[r * ASTR + c + 4]);
                    af[mt][3] = __float_as_uint(Ab[(r + 8) * ASTR + c + 4]);
                }
                uint32_t bf[4][2];
                #pragma unroll
                for (int nt = 0; nt < 4; nt++) {
                    int n = wn * 32 + nt * 8 + g;
                    int c = ks * 8 + tg;
                    bf[nt][0] = __float_as_uint(Bb[n * ASTR + c]);
                    bf[nt][1] = __float_as_uint(Bb[n * ASTR + c + 4]);
                }
                #pragma unroll
                for (int mt = 0; mt < 4; mt++)
                    #pragma unroll
                    for (int nt = 0; nt < 4; nt++) {
                        asm volatile(
                            "mma.sync.aligned.m16n8k8.row.col.f32.tf32.tf32.f32 "
                            "{%0,%1,%2,%3}, {%4,%5,%6,%7}, {%8,%9}, {%0,%1,%2,%3};\n"
                            : "+f"(s_acc[mt][nt][0]), "+f"(s_acc[mt][nt][1]),
                              "+f"(s_acc[mt][nt][2]), "+f"(s_acc[mt][nt][3])
                            : "r"(af[mt][0]), "r"(af[mt][1]), "r"(af[mt][2]), "r"(af[mt][3]),
                              "r"(bf[nt][0]), "r"(bf[nt][1]));
                    }
            }
            __syncthreads();
        }

        // ================= online softmax =================
        float rmax[4][2];
        #pragma unroll
        for (int mt = 0; mt < 4; mt++) {
            #pragma unroll
            for (int h = 0; h < 2; h++) {
                int row = bm0 + wm * 64 + mt * 16 + g + h * 8;
                const int* mrow = Mp + (size_t)row * S_ + bn0;
                float mx = -INFINITY;
                #pragma unroll
                for (int nt = 0; nt < 4; nt++) {
                    int2 mk = *reinterpret_cast<const int2*>(mrow + wn * 32 + nt * 8 + tg * 2);
                    float vx = (mk.x > 0) ? s_acc[mt][nt][h * 2 + 0] * SC : -INFINITY;
                    float vy = (mk.y > 0) ? s_acc[mt][nt][h * 2 + 1] * SC : -INFINITY;
                    s_acc[mt][nt][h * 2 + 0] = vx;
                    s_acc[mt][nt][h * 2 + 1] = vy;
                    mx = fmaxf(mx, fmaxf(vx, vy));
                }
                mx = fmaxf(mx, __shfl_xor_sync(0xffffffffu, mx, 1));
                mx = fmaxf(mx, __shfl_xor_sync(0xffffffffu, mx, 2));
                rmax[mt][h] = mx;
            }
        }
        if (tg == 0) {
            #pragma unroll
            for (int mt = 0; mt < 4; mt++)
                #pragma unroll
                for (int h = 0; h < 2; h++)
                    redm[wn * 128 + wm * 64 + mt * 16 + g + h * 8] = rmax[mt][h];
        }
        __syncthreads();

        float corr_s[4][2];
        #pragma unroll
        for (int mt = 0; mt < 4; mt++) {
            #pragma unroll
            for (int h = 0; h < 2; h++) {
                int rl = wm * 64 + mt * 16 + g + h * 8;
                float tm = fmaxf(fmaxf(redm[rl], redm[128 + rl]),
                                 fmaxf(redm[256 + rl], redm[384 + rl]));
                float mo = m_i[mt][h];
                float mnew = fmaxf(mo, tm);
                float corr = (mo == -INFINITY) ? 0.f : __expf(mo - mnew);
                float s = 0.f;
                #pragma unroll
                for (int nt = 0; nt < 4; nt++) {
                    float px = tf32r(__expf(s_acc[mt][nt][h * 2 + 0] - mnew));
                    float py = tf32r(__expf(s_acc[mt][nt][h * 2 + 1] - mnew));
                    s += px + py;
                    *reinterpret_cast<float2*>(&Ps[rl * 132 + wn * 32 + nt * 8 + tg * 2]) =
                        make_float2(px, py);
                }
                s += __shfl_xor_sync(0xffffffffu, s, 1);
                s += __shfl_xor_sync(0xffffffffu, s, 2);
                if (tg == 0) reds[wn * 128 + rl] = s;
                m_i[mt][h]  = mnew;
                corr_s[mt][h] = corr;
                #pragma unroll
                for (int nt = 0; nt < 4; nt++) {
                    o_acc[mt][nt][h * 2 + 0] *= corr;
                    o_acc[mt][nt][h * 2 + 1] *= corr;
                }
            }
        }
        __syncthreads();
        #pragma unroll
        for (int mt = 0; mt < 4; mt++)
            #pragma unroll
            for (int h = 0; h < 2; h++) {
                int rl = wm * 64 + mt * 16 + g + h * 8;
                float ts = reds[rl] + reds[128 + rl] + reds[256 + rl] + reds[384 + rl];
                l_i[mt][h] = l_i[mt][h] * corr_s[mt][h] + ts;
            }

        // ================= O += P @ V =================
        load_v(0, bn0, 0);
        CP_COMMIT();
        #pragma unroll
        for (int kc = 0; kc < 4; kc++) {
            CP_WAIT0();
            __syncthreads();
            if (kc < 3) { load_v((kc + 1) & 1, bn0, (kc + 1) * 32); CP_COMMIT(); }
            const float* Bb = Bs + (kc & 1) * 128 * ASTR;
            #pragma unroll
            for (int ks = 0; ks < 4; ks++) {
                uint32_t af[4][4];
                #pragma unroll
                for (int mt = 0; mt < 4; mt++) {
                    int r = wm * 64 + mt * 16 + g;
                    int c = kc * 32 + ks * 8 + tg;
                    af[mt][0] = __float_as_uint(Ps[r * 132 + c]);
                    af[mt][1] = __float_as_uint(Ps[(r + 8) * 132 + c]);
                    af[mt][2] = __float_as_uint(Ps[r * 132 + c + 4]);
                    af[mt][3] = __float_as_uint(Ps[(r + 8) * 132 + c + 4]);
                }
                uint32_t bf[4][2];
                #pragma unroll
                for (int nt = 0; nt < 4; nt++) {
                    int n = wn * 32 + nt * 8 + g;
                    int c = ks * 8 + tg;
                    bf[nt][0] = __float_as_uint(Bb[n * ASTR + c]);
                    bf[nt][1] = __float_as_uint(Bb[n * ASTR + c + 4]);
                }
                #pragma unroll
                for (int mt = 0; mt < 4; mt++)
                    #pragma unroll
                    for (int nt = 0; nt < 4; nt++) {
                        asm volatile(
                            "mma.sync.aligned.m16n8k8.row.col.f32.tf32.tf32.f32 "
                            "{%0,%1,%2,%3}, {%4,%5,%6,%7}, {%8,%9}, {%0,%1,%2,%3};\n"
                            : "+f"(o_acc[mt][nt][0]), "+f"(o_acc[mt][nt][1]),
                              "+f"(o_acc[mt][nt][2]), "+f"(o_acc[mt][nt][3])
                            : "r"(af[mt][0]), "r"(af[mt][1]), "r"(af[mt][2]), "r"(af[mt][3]),
                              "r"(bf[nt][0]), "r"(bf[nt][1]));
                    }
            }
            __syncthreads();
        }
    }

    // ---- epilogue: normalize and store ----
    #pragma unroll
    for (int mt = 0; mt < 4; mt++) {
        #pragma unroll
        for (int h = 0; h < 2; h++) {
            int rl = wm * 64 + mt * 16 + g + h * 8;
            float inv = 1.f / l_i[mt][h];
            float* orow = O + ((size_t)b * S_ + (bm0 + rl)) * H_ + hhead * HD_;
            #pragma unroll
            for (int nt = 0; nt < 4; nt++) {
                int c = wn * 32 + nt * 8 + tg * 2;
                *reinterpret_cast<float2*>(orow + c) =
                    make_float2(tf32r(o_acc[mt][nt][h * 2 + 0] * inv),
                                tf32r(o_acc[mt][nt][h * 2 + 1] * inv));
            }
        }
    }
}

// ---------------------------------------------------------------------------
// Host driver
// ---------------------------------------------------------------------------
extern "C" void kernel_launch(void* const* d_in, const int* in_sizes, int n_in,
                              void* d_out, int out_size)
{
    const float* fused  = (const float*)d_in[0];
    const int*   mask   = (const int*)  d_in[1];
    const int*   nvp    = (const int*)  d_in[2];
    const float* ln1_g  = (const float*)d_in[4];
    const float* ln1_b  = (const float*)d_in[5];
    const float* wq     = (const float*)d_in[6];
    const float* bq     = (const float*)d_in[7];
    const float* wk     = (const float*)d_in[8];
    const float* bk     = (const float*)d_in[9];
    const float* wv     = (const float*)d_in[10];
    const float* bv     = (const float*)d_in[11];
    const float* wm     = (const float*)d_in[12];
    const float* bmp    = (const float*)d_in[13];
    const float* ln2v_g = (const float*)d_in[14];
    const float* ln2v_b = (const float*)d_in[15];
    const float* fv1_w  = (const float*)d_in[16];
    const float* fv1_b  = (const float*)d_in[17];
    const float* fv2_w  = (const float*)d_in[18];
    const float* fv2_b  = (const float*)d_in[19];
    const float* ln2t_g = (const float*)d_in[20];
    const float* ln2t_b = (const float*)d_in[21];
    const float* ft1_w  = (const float*)d_in[22];
    const float* ft1_b  = (const float*)d_in[23];
    const float* ft2_w  = (const float*)d_in[24];
    const float* ft2_b  = (const float*)d_in[25];

    float* base = nullptr;
    cudaGetSymbolAddress((void**)&base, g_buf);
    float* xn  = base;
    float* qb  = base + 1 * XSZ;
    float* kb  = base + 2 * XSZ;
    float* vb  = base + 3 * XSZ;   // Vt layout [B*NH, HD, S]
    float* rb  = base + 4 * XSZ;
    float* xb  = base + 5 * XSZ;
    float* hb  = base + 6 * XSZ;
    float* wt  = base + 6 * XSZ + HSZ;
    float* wq_t  = wt;
    float* wk_t  = wt + 1 * WSQ;
    float* wv_t  = wt + 2 * WSQ;
    float* wm_t  = wt + 3 * WSQ;
    float* fv1_t = wt + 4 * WSQ;
    float* ft1_t = fv1_t + WSF;
    float* fv2_t = ft1_t + WSF;
    float* ft2_t = fv2_t + WSF;

    cudaFuncSetAttribute(flash_tc,
                         cudaFuncAttributeMaxDynamicSharedMemorySize, FTC_SMEM);
    cudaFuncSetAttribute(gemm_tc<0>,
                         cudaFuncAttributeMaxDynamicSharedMemorySize, GEMM_SMEM);
    cudaFuncSetAttribute(gemm_tc<3>,
                         cudaFuncAttributeMaxDynamicSharedMemorySize, GEMM_SMEM);
    cudaFuncSetAttribute(gemm_tc<4>,
                         cudaFuncAttributeMaxDynamicSharedMemorySize, GEMM_SMEM);
    cudaFuncSetAttribute(gemm_tc<5>,
                         cudaFuncAttributeMaxDynamicSharedMemorySize, GEMM_SMEM);

    // ---- one-time tf32 weight prep ----
    {
        int nq4 = (int)(WSQ / 4), nf4 = (int)(WSF / 4);
        int tq = 256, gq = (nq4 + tq - 1) / tq, gf = (nf4 + tq - 1) / tq;
        round_tf32_k<<<gq, tq>>>(wq, wq_t, nq4);
        round_tf32_k<<<gq, tq>>>(wk, wk_t, nq4);
        round_tf32_k<<<gq, tq>>>(wv, wv_t, nq4);
        round_tf32_k<<<gq, tq>>>(wm, wm_t, nq4);
        round_tf32_k<<<gf, tq>>>(fv1_w, fv1_t, nf4);
        round_tf32_k<<<gf, tq>>>(ft1_w, ft1_t, nf4);
        round_tf32_k<<<gf, tq>>>(fv2_w, fv2_t, nf4);
        round_tf32_k<<<gf, tq>>>(ft2_w, ft2_t, nf4);
    }

    dim3 thr(256);
    dim3 gProj(H_ / 128, M_ / 128);            // (8, 48)
    dim3 gF1(FF_ / 128, M_ / 128);             // (32, 48)
    dim3 gFl(S_ / 128, B_ * NH_);              // (12, 32)

    const float* xc = fused;
    for (int layer = 0; layer < 6; layer++) {
        float* xnext = (layer == 5) ? (float*)d_out : xb;

        // ---- attention block ----
        ln_kernel<<<M_, thr>>>(xc, ln1_g, ln1_b, nullptr, nullptr, nullptr, xn);
        gemm_tc<0><<<gProj, thr, GEMM_SMEM>>>(xn, wq_t, bq, nullptr, qb, M_, H_, H_, nullptr, nullptr, nullptr);
        gemm_tc<0><<<gProj, thr, GEMM_SMEM>>>(xn, wk_t, bk, nullptr, kb, M_, H_, H_, nullptr, nullptr, nullptr);
        gemm_tc<5><<<gProj, thr, GEMM_SMEM>>>(xn, wv_t, bv, nullptr, vb, M_, H_, H_, nullptr, nullptr, nullptr);
        flash_tc<<<gFl, thr, FTC_SMEM>>>(qb, kb, vb, mask, xn);
        gemm_tc<3><<<gProj, thr, GEMM_SMEM>>>(xn, wm_t, bmp, xc, rb, M_, H_, H_, nullptr, nullptr, nullptr);

        // ---- split FFN block ----
        ln_kernel<<<M_, thr>>>(rb, ln2v_g, ln2v_b, ln2t_g, ln2t_b, nvp, xn);
        gemm_tc<4><<<gF1, thr, GEMM_SMEM>>>(xn, fv1_t, fv1_b, nullptr, hb, M_, FF_, H_, ft1_t, ft1_b, nvp);
        gemm_tc<3><<<gProj, thr, GEMM_SMEM>>>(hb, fv2_t, fv2_b, rb, xnext, M_, H_, FF_, ft2_t, ft2_b, nvp);

        xc = xnext;
    }
}